// round 12
// baseline (speedup 1.0000x reference)
#include <cuda_runtime.h>
#include <cuda_fp16.h>
#include <cstdint>

#define N_NODES  50000
#define N_EDGES  400000
#define N_GRAPHS 64

// ============================ device scratch ===============================
__device__ __half g_w1[256 * 512];         // [W1l|W1r]^T fp16  [256 n][512 k]
__device__ __half g_w2[64 * 128];          // [W2l|W2r]^T fp16  [64 n][128 k]
__device__ __half g_y1l[N_NODES * 128];    // x@W1l (fp16, for edge gather)
__device__ float  g_y1r[N_NODES * 128];    // x@W1r (fp32)
__device__ __half g_agg1[N_NODES * 128];   // fp16 edge-sum accumulator
__device__ float  g_cnt[N_NODES];
__device__ __half g_y2l[N_NODES * 32];     // h1@W2l (fp16)
__device__ float  g_y2r[N_NODES * 32];     // h1@W2r (fp32)
__device__ __half g_agg2[N_NODES * 32];    // fp16 edge-sum accumulator
__device__ float  g_gsum[N_GRAPHS * 32];
__device__ float  g_gcnt[N_GRAPHS];

// ============== setup: zero accumulators + weight conversion ===============
__global__ void setup_kernel(const float* __restrict__ W1l, const float* __restrict__ W1r,
                             const float* __restrict__ W2l, const float* __restrict__ W2r) {
    size_t i = (size_t)blockIdx.x * blockDim.x + threadIdx.x;
    size_t stride = (size_t)gridDim.x * blockDim.x;
    for (size_t k = i; k < (size_t)N_NODES * 64; k += stride) ((uint32_t*)g_agg1)[k] = 0u;
    for (size_t k = i; k < (size_t)N_NODES * 16; k += stride) ((uint32_t*)g_agg2)[k] = 0u;
    for (size_t k = i; k < (size_t)N_NODES;      k += stride) g_cnt[k]  = 0.f;
    for (size_t k = i; k < (size_t)N_GRAPHS * 32; k += stride) g_gsum[k] = 0.f;
    for (size_t k = i; k < (size_t)N_GRAPHS;      k += stride) g_gcnt[k] = 0.f;
    for (size_t idx = i; idx < 256 * 512; idx += stride) {
        int n = (int)(idx >> 9), k = (int)(idx & 511);
        float v = (n < 128) ? W1l[k * 128 + n] : W1r[k * 128 + (n - 128)];
        g_w1[idx] = __float2half_rn(v);
    }
    for (size_t idx = i; idx < 64 * 128; idx += stride) {
        int n = (int)(idx >> 7), k = (int)(idx & 127);
        float v = (n < 32) ? W2l[k * 32 + n] : W2r[k * 32 + (n - 32)];
        g_w2[idx] = __float2half_rn(v);
    }
}

// ============================ helpers ======================================
__device__ __forceinline__ uint32_t su32(const void* p) {
    return (uint32_t)__cvta_generic_to_shared(p);
}
__device__ __forceinline__ uint32_t pack_h2(__half a, __half b) {
    __half2 t = __halves2half2(a, b);
    return *(uint32_t*)&t;
}
__device__ __forceinline__ uint2 cvt4h(float4 v) {
    return make_uint2(pack_h2(__float2half_rn(v.x), __float2half_rn(v.y)),
                      pack_h2(__float2half_rn(v.z), __float2half_rn(v.w)));
}
__device__ __forceinline__ void mma16816h(float* c, const uint32_t* a, const uint32_t* b) {
    asm volatile(
        "mma.sync.aligned.m16n8k16.row.col.f32.f16.f16.f32 "
        "{%0,%1,%2,%3}, {%4,%5,%6,%7}, {%8,%9}, {%0,%1,%2,%3};"
        : "+f"(c[0]), "+f"(c[1]), "+f"(c[2]), "+f"(c[3])
        : "r"(a[0]), "r"(a[1]), "r"(a[2]), "r"(a[3]), "r"(b[0]), "r"(b[1]));
}
__device__ __forceinline__ void ldsm4(uint32_t* r, uint32_t addr) {
    asm volatile("ldmatrix.sync.aligned.m8n8.x4.shared.b16 {%0,%1,%2,%3}, [%4];"
                 : "=r"(r[0]), "=r"(r[1]), "=r"(r[2]), "=r"(r[3]) : "r"(addr));
}
__device__ __forceinline__ void red_h8(__half* p, uint4 v) {
    asm volatile("red.global.add.noftz.v4.f16x2 [%0], {%1,%2,%3,%4};"
                 :: "l"(p), "r"(v.x), "r"(v.y), "r"(v.z), "r"(v.w) : "memory");
}

// ===== GEMM1: [y1l|y1r] = x[M,512] @ W1^T  (fp16, fused convert, BK=64) ====
// 512 threads, CTA tile 128(M) x 256(N), BK=64, 3-stage store-early pipeline.
#define G1_ROW 144
#define G1_STAGE 55296
#define SM_G1 (3 * G1_STAGE)

__global__ __launch_bounds__(512) void gemm1_mma(const float* __restrict__ x, int M) {
    extern __shared__ char smem[];
    const uint32_t sb = su32(smem);
    const int tid  = threadIdx.x;
    const int lane = tid & 31, wid = tid >> 5;
    const int wm = (wid & 3) * 32;
    const int wn = (wid >> 2) * 64;
    const int rowBase = blockIdx.x * 128;

    float acc[2][8][4];
#pragma unroll
    for (int i = 0; i < 2; i++)
#pragma unroll
        for (int j = 0; j < 8; j++)
#pragma unroll
            for (int q = 0; q < 4; q++) acc[i][j][q] = 0.f;

    const int g4 = lane & 3, gID = lane >> 2;
    const int sel = lane >> 3;
    const uint32_t rowInSel = (uint32_t)((sel & 1) * 8 + (lane & 7));
    const uint32_t colSel = (uint32_t)((sel >> 1) * 16);
    const uint32_t aOff = (wm + rowInSel) * G1_ROW + colSel;
    const uint32_t bOff = 18432 + (wn + rowInSel) * G1_ROW + colSel;

    const int arow = tid >> 2, aq = tid & 3;
    const int gra = rowBase + arow;
    const bool av = (gra < M);
    const size_t agi = (size_t)(av ? gra : 0) * 512 + aq * 16;
    const uint32_t sAo = arow * G1_ROW + aq * 32;
    const uint32_t bRow0 = tid >> 3, bQ = (uint32_t)(tid & 7);
    const size_t bgiBase = (size_t)bRow0 * 512 + bQ * 8;
    const uint32_t sBoBase = 18432 + bRow0 * G1_ROW + bQ * 16;

    float4 ra[4];
    uint4 rb[4];
    const float4 zf4 = make_float4(0.f, 0.f, 0.f, 0.f);

    auto loadRegs = [&](int kt) {
#pragma unroll
        for (int p = 0; p < 4; p++)
            ra[p] = av ? *(const float4*)(x + agi + kt + p * 4) : zf4;
#pragma unroll
        for (int p = 0; p < 4; p++)
            rb[p] = *(const uint4*)(g_w1 + bgiBase + (size_t)p * 64 * 512 + kt);
    };
    auto storeStage = [&](int s) {
        char* st = smem + s * G1_STAGE;
        uint2 h0 = cvt4h(ra[0]), h1 = cvt4h(ra[1]);
        *(uint4*)(st + sAo)      = make_uint4(h0.x, h0.y, h1.x, h1.y);
        h0 = cvt4h(ra[2]); h1 = cvt4h(ra[3]);
        *(uint4*)(st + sAo + 16) = make_uint4(h0.x, h0.y, h1.x, h1.y);
#pragma unroll
        for (int p = 0; p < 4; p++)
            *(uint4*)(st + sBoBase + p * (64 * G1_ROW)) = rb[p];
    };

    loadRegs(0);
    storeStage(0);
    loadRegs(64);
    __syncthreads();

    for (int it = 0; it < 8; it++) {
        if (it < 7) storeStage((it + 1) % 3);
        if (it < 6) loadRegs((it + 2) * 64);
        __syncthreads();

        const uint32_t Ab = sb + (uint32_t)(it % 3) * G1_STAGE;
#pragma unroll
        for (int kk2 = 0; kk2 < 4; kk2++) {
            uint32_t a[2][4];
            ldsm4(a[0], Ab + aOff + kk2 * 32);
            ldsm4(a[1], Ab + aOff + 2304 + kk2 * 32);
#pragma unroll
            for (int ntp = 0; ntp < 4; ntp++) {
                uint32_t b[4];
                ldsm4(b, Ab + bOff + ntp * 2304 + kk2 * 32);
                uint32_t b0[2] = {b[0], b[2]};
                uint32_t b1[2] = {b[1], b[3]};
                mma16816h(acc[0][2 * ntp],     a[0], b0);
                mma16816h(acc[1][2 * ntp],     a[1], b0);
                mma16816h(acc[0][2 * ntp + 1], a[0], b1);
                mma16816h(acc[1][2 * ntp + 1], a[1], b1);
            }
        }
    }

    // epilogue: cols < 128 -> y1l fp16 ; cols >= 128 -> y1r fp32
#pragma unroll
    for (int mt = 0; mt < 2; mt++) {
        int r0 = rowBase + wm + mt * 16 + gID;
#pragma unroll
        for (int nt = 0; nt < 8; nt++) {
            int cc = wn + nt * 8 + g4 * 2;
            if (wn < 128) {
                uint32_t p0 = pack_h2(__float2half_rn(acc[mt][nt][0]),
                                      __float2half_rn(acc[mt][nt][1]));
                uint32_t p1 = pack_h2(__float2half_rn(acc[mt][nt][2]),
                                      __float2half_rn(acc[mt][nt][3]));
                if (r0 < M)     *(uint32_t*)(g_y1l + (size_t)r0 * 128 + cc) = p0;
                if (r0 + 8 < M) *(uint32_t*)(g_y1l + (size_t)(r0 + 8) * 128 + cc) = p1;
            } else {
                int cr = cc - 128;
                if (r0 < M)
                    *(float2*)(g_y1r + (size_t)r0 * 128 + cr) =
                        make_float2(acc[mt][nt][0], acc[mt][nt][1]);
                if (r0 + 8 < M)
                    *(float2*)(g_y1r + (size_t)(r0 + 8) * 128 + cr) =
                        make_float2(acc[mt][nt][2], acc[mt][nt][3]);
            }
        }
    }
}

// ===== GEMM2 (fused SAGE epilogue): K=128 loaded once, single sync =========
// 256 threads, tile 128(M) x 64(N). smem rows 272 B (conflict-free ldsm).
#define G2_B 34816
#define SM_G2 (34816 + 64 * 272)

__global__ __launch_bounds__(256) void gemm2_mma(const float* __restrict__ b1l, int M) {
    extern __shared__ char smem[];
    const uint32_t sB0 = su32(smem);
    const int tid  = threadIdx.x;
    const int lane = tid & 31, wid = tid >> 5;
    const int wm = (wid & 3) * 32;
    const int wn = (wid >> 2) * 32;
    const int rowBase = blockIdx.x * 128;

    float acc[2][4][4];
#pragma unroll
    for (int i = 0; i < 2; i++)
#pragma unroll
        for (int j = 0; j < 4; j++)
#pragma unroll
            for (int q = 0; q < 4; q++) acc[i][j][q] = 0.f;

    const int g4 = lane & 3, gID = lane >> 2;
    const int sel = lane >> 3;
    const uint32_t rowInSel = (uint32_t)((sel & 1) * 8 + (lane & 7));
    const uint32_t colSel = (uint32_t)((sel >> 1) * 16);
    const uint32_t aOff = (wm + rowInSel) * 272 + colSel;
    const uint32_t bOff = G2_B + (wn + rowInSel) * 272 + colSel;

    // ---- A: fused SAGE epilogue (one row-half per thread: 64 k values) ----
    {
        const int arow = tid >> 1;          // 0..127
        const int ahalf = tid & 1;          // k half
        const int gr = rowBase + arow;
        const bool av = (gr < M);
        const float inv = av ? 1.0f / fmaxf(g_cnt[gr], 1.0f) : 0.f;
#pragma unroll
        for (int c = 0; c < 8; c++) {
            const int kc = ahalf * 64 + c * 8;
            uint4 packed = make_uint4(0, 0, 0, 0);
            if (av) {
                uint4 au = *(const uint4*)(g_agg1 + (size_t)gr * 128 + kc);
                const __half2* ah = (const __half2*)&au;
                float2 a0 = __half22float2(ah[0]), a1 = __half22float2(ah[1]);
                float2 a2 = __half22float2(ah[2]), a3 = __half22float2(ah[3]);
                float4 r0 = *(const float4*)(g_y1r + (size_t)gr * 128 + kc);
                float4 r1 = *(const float4*)(g_y1r + (size_t)gr * 128 + kc + 4);
                float4 bb0 = *(const float4*)(b1l + kc);
                float4 bb1 = *(const float4*)(b1l + kc + 4);
                float4 o0, o1;
                o0.x = fmaxf(a0.x * inv + bb0.x + r0.x, 0.f);
                o0.y = fmaxf(a0.y * inv + bb0.y + r0.y, 0.f);
                o0.z = fmaxf(a1.x * inv + bb0.z + r0.z, 0.f);
                o0.w = fmaxf(a1.y * inv + bb0.w + r0.w, 0.f);
                o1.x = fmaxf(a2.x * inv + bb1.x + r1.x, 0.f);
                o1.y = fmaxf(a2.y * inv + bb1.y + r1.y, 0.f);
                o1.z = fmaxf(a3.x * inv + bb1.z + r1.z, 0.f);
                o1.w = fmaxf(a3.y * inv + bb1.w + r1.w, 0.f);
                uint2 h0 = cvt4h(o0), h1 = cvt4h(o1);
                packed = make_uint4(h0.x, h0.y, h1.x, h1.y);
            }
            *(uint4*)(smem + arow * 272 + kc * 2) = packed;
        }
    }
    // ---- B: 64 rows x 128 halves = 1024 chunks -> 4/thread ----
    {
        const int brow = tid >> 2;
        const int bq0 = (tid & 3) * 4;
#pragma unroll
        for (int c = 0; c < 4; c++) {
            int q = bq0 + c;
            *(uint4*)(smem + G2_B + brow * 272 + q * 16) =
                *(const uint4*)(g_w2 + (size_t)brow * 128 + q * 8);
        }
    }
    __syncthreads();

#pragma unroll
    for (int kk2 = 0; kk2 < 8; kk2++) {
        uint32_t a[2][4];
        ldsm4(a[0], sB0 + aOff + kk2 * 32);
        ldsm4(a[1], sB0 + aOff + 4352 + kk2 * 32);
#pragma unroll
        for (int ntp = 0; ntp < 2; ntp++) {
            uint32_t b[4];
            ldsm4(b, sB0 + bOff + ntp * 4352 + kk2 * 32);
            uint32_t b0[2] = {b[0], b[2]};
            uint32_t b1[2] = {b[1], b[3]};
            mma16816h(acc[0][2 * ntp],     a[0], b0);
            mma16816h(acc[1][2 * ntp],     a[1], b0);
            mma16816h(acc[0][2 * ntp + 1], a[0], b1);
            mma16816h(acc[1][2 * ntp + 1], a[1], b1);
        }
    }

    // epilogue: cols < 32 -> y2l fp16 ; cols >= 32 -> y2r fp32
#pragma unroll
    for (int mt = 0; mt < 2; mt++) {
        int r0 = rowBase + wm + mt * 16 + gID;
#pragma unroll
        for (int nt = 0; nt < 4; nt++) {
            int cc = wn + nt * 8 + g4 * 2;
            if (cc < 32) {
                uint32_t p0 = pack_h2(__float2half_rn(acc[mt][nt][0]),
                                      __float2half_rn(acc[mt][nt][1]));
                uint32_t p1 = pack_h2(__float2half_rn(acc[mt][nt][2]),
                                      __float2half_rn(acc[mt][nt][3]));
                if (r0 < M)     *(uint32_t*)(g_y2l + (size_t)r0 * 32 + cc) = p0;
                if (r0 + 8 < M) *(uint32_t*)(g_y2l + (size_t)(r0 + 8) * 32 + cc) = p1;
            } else {
                int cr = cc - 32;
                if (r0 < M)
                    *(float2*)(g_y2r + (size_t)r0 * 32 + cr) =
                        make_float2(acc[mt][nt][0], acc[mt][nt][1]);
                if (r0 + 8 < M)
                    *(float2*)(g_y2r + (size_t)(r0 + 8) * 32 + cr) =
                        make_float2(acc[mt][nt][2], acc[mt][nt][3]);
            }
        }
    }
}

// -------- edge aggregation, layer 1 (128 fp16 feats, 16 threads/edge) ------
__global__ void edge_agg1(const int* __restrict__ ei) {
    int gtid = blockIdx.x * blockDim.x + threadIdx.x;
    int e = gtid >> 4;
    int lane = gtid & 15;
    if (e >= N_EDGES) return;
    int src = ei[e];
    int dst = ei[N_EDGES + e];
    uint4 v = *(const uint4*)(g_y1l + (size_t)src * 128 + lane * 8);
    red_h8(g_agg1 + (size_t)dst * 128 + lane * 8, v);
    if (lane == 0) atomicAdd(&g_cnt[dst], 1.0f);
}

// -------- edge aggregation, layer 2 (32 fp16 feats, 4 threads/edge) --------
__global__ void edge_agg2(const int* __restrict__ ei) {
    int gtid = blockIdx.x * blockDim.x + threadIdx.x;
    int e = gtid >> 2;
    int lane = gtid & 3;
    if (e >= N_EDGES) return;
    int src = ei[e];
    int dst = ei[N_EDGES + e];
    uint4 v = *(const uint4*)(g_y2l + (size_t)src * 32 + lane * 8);
    red_h8(g_agg2 + (size_t)dst * 32 + lane * 8, v);
}

// ---------------- fused layer-2 epilogue + per-graph mean pool --------------
__global__ void pool_kernel(const int* __restrict__ batch, const float* __restrict__ b2l) {
    int f = threadIdx.x;           // 32
    int yid = threadIdx.y;         // 8
    int n0 = blockIdx.x * 512 + yid;
    float b = b2l[f];
    float acc = 0.f, cacc = 0.f;
    int cur = -1;
    for (int it = 0; it < 64; it++) {
        int n = n0 + it * 8;
        if (n < N_NODES) {
            int g = batch[n];
            if (g != cur) {
                if (cur >= 0) {
                    atomicAdd(&g_gsum[cur * 32 + f], acc);
                    if (f == 0) atomicAdd(&g_gcnt[cur], cacc);
                }
                cur = g; acc = 0.f; cacc = 0.f;
            }
            float inv = 1.0f / fmaxf(g_cnt[n], 1.0f);
            float v = __half2float(g_agg2[(size_t)n * 32 + f]) * inv + b +
                      g_y2r[(size_t)n * 32 + f];
            acc += fmaxf(v, 0.f);
            cacc += 1.f;
        }
    }
    if (cur >= 0) {
        atomicAdd(&g_gsum[cur * 32 + f], acc);
        if (f == 0) atomicAdd(&g_gcnt[cur], cacc);
    }
}

// ---------------- final tiny MLP (encoder head + decoder) ------------------
__global__ void mlp_kernel(const float* __restrict__ Wl1, const float* __restrict__ bl1,
                           const float* __restrict__ Wl2, const float* __restrict__ bl2,
                           const float* __restrict__ Wd1, const float* __restrict__ bd1,
                           const float* __restrict__ Wd2, const float* __restrict__ bd2,
                           const float* __restrict__ Wd3, const float* __restrict__ bd3,
                           float* __restrict__ out) {
    __shared__ float sWl1[1024], sWl2[512], sWd1[512], sWd2[1024], sWd3[1600];
    __shared__ float sbl1[32], sbl2[16], sbd1[32], sbd2[32], sbd3[50];
    int t = threadIdx.x;           // 64
    for (int i = t; i < 1024; i += 64) sWl1[i] = Wl1[i];
    for (int i = t; i < 512;  i += 64) sWl2[i] = Wl2[i];
    for (int i = t; i < 512;  i += 64) sWd1[i] = Wd1[i];
    for (int i = t; i < 1024; i += 64) sWd2[i] = Wd2[i];
    for (int i = t; i < 1600; i += 64) sWd3[i] = Wd3[i];
    if (t < 32) sbl1[t] = bl1[t];
    if (t < 16) sbl2[t] = bl2[t];
    if (t < 32) sbd1[t] = bd1[t];
    if (t < 32) sbd2[t] = bd2[t];
    for (int i = t; i < 50; i += 64) sbd3[i] = bd3[i];
    __syncthreads();
    if (t >= N_GRAPHS) return;

    float gv[32];
    float inv = 1.0f / fmaxf(g_gcnt[t], 1.0f);
#pragma unroll
    for (int i = 0; i < 32; i++) gv[i] = g_gsum[t * 32 + i] * inv;

    float a[32];
#pragma unroll
    for (int j = 0; j < 32; j++) {
        float s = sbl1[j];
#pragma unroll
        for (int i = 0; i < 32; i++) s = fmaf(gv[i], sWl1[i * 32 + j], s);
        a[j] = fmaxf(s, 0.f);
    }
    float enc[16];
#pragma unroll
    for (int j = 0; j < 16; j++) {
        float s = sbl2[j];
#pragma unroll
        for (int i = 0; i < 32; i++) s = fmaf(a[i], sWl2[i * 16 + j], s);
        enc[j] = s > 0.f ? s : 0.1f * s;
    }
#pragma unroll
    for (int j = 0; j < 16; j++) out[t * 16 + j] = enc[j];

    float z1[32];
#pragma unroll
    for (int j = 0; j < 32; j++) {
        float s = sbd1[j];
#pragma unroll
        for (int i = 0; i < 16; i++) s = fmaf(enc[i], sWd1[i * 32 + j], s);
        z1[j] = s > 0.f ? s : 0.1f * s;
    }
    float z2[32];
#pragma unroll
    for (int j = 0; j < 32; j++) {
        float s = sbd2[j];
#pragma unroll
        for (int i = 0; i < 32; i++) s = fmaf(z1[i], sWd2[i * 32 + j], s);
        z2[j] = s > 0.f ? s : 0.1f * s;
    }
#pragma unroll
    for (int j = 0; j < 50; j++) {
        float s = sbd3[j];
#pragma unroll
        for (int i = 0; i < 32; i++) s = fmaf(z2[i], sWd3[i * 50 + j], s);
        out[1024 + t * 50 + j] = s;
    }
}

// ---------------- launch ----------------------------------------------------
extern "C" void kernel_launch(void* const* d_in, const int* in_sizes, int n_in,
                              void* d_out, int out_size) {
    const float* x   = (const float*)d_in[0];
    const int*   ei  = (const int*)d_in[1];
    const int*   bat = (const int*)d_in[2];
    const float* W1l = (const float*)d_in[3];
    const float* b1l = (const float*)d_in[4];
    const float* W1r = (const float*)d_in[5];
    const float* W2l = (const float*)d_in[6];
    const float* b2l = (const float*)d_in[7];
    const float* W2r = (const float*)d_in[8];
    const float* Wl1 = (const float*)d_in[9];
    const float* bl1 = (const float*)d_in[10];
    const float* Wl2 = (const float*)d_in[11];
    const float* bl2 = (const float*)d_in[12];
    const float* Wd1 = (const float*)d_in[13];
    const float* bd1 = (const float*)d_in[14];
    const float* Wd2 = (const float*)d_in[15];
    const float* bd2 = (const float*)d_in[16];
    const float* Wd3 = (const float*)d_in[17];
    const float* bd3 = (const float*)d_in[18];
    float* out = (float*)d_out;

    static bool attr_set = false;
    if (!attr_set) {
        cudaFuncSetAttribute(gemm1_mma, cudaFuncAttributeMaxDynamicSharedMemorySize, SM_G1);
        cudaFuncSetAttribute(gemm2_mma, cudaFuncAttributeMaxDynamicSharedMemorySize, SM_G2);
        attr_set = true;
    }

    setup_kernel<<<592, 256>>>(W1l, W1r, W2l, W2r);

    // GEMM1 (tensor pipe, fp16, fused convert, BK=64, 3-stage pipeline)
    gemm1_mma<<<(N_NODES + 127) / 128, 512, SM_G1>>>(x, N_NODES);

    edge_agg1<<<25000, 256>>>(ei);   // fp16 v4 reductions, 16 thr/edge

    // GEMM2 (tensor pipe, fused SAGE epilogue, single-shot K)
    gemm2_mma<<<(N_NODES + 127) / 128, 256, SM_G2>>>(b1l, N_NODES);

    edge_agg2<<<6250, 256>>>(ei);    // fp16 v4 reductions, 4 thr/edge

    {
        dim3 blk(32, 8);
        pool_kernel<<<(N_NODES + 511) / 512, blk>>>(bat, b2l);
    }

    mlp_kernel<<<1, 64>>>(Wl1, bl1, Wl2, bl2, Wd1, bd1, Wd2, bd2, Wd3, bd3, out);
}

// round 13
// speedup vs baseline: 1.0433x; 1.0433x over previous
#include <cuda_runtime.h>
#include <cuda_fp16.h>
#include <cstdint>

#define N_NODES  50000
#define N_EDGES  400000
#define N_GRAPHS 64

// ============================ device scratch ===============================
__device__ __half g_w1[256 * 512];         // [W1l|W1r]^T fp16  [256 n][512 k]
__device__ __half g_w2[64 * 128];          // [W2l|W2r]^T fp16  [64 n][128 k]
__device__ __half g_y1l[N_NODES * 128];    // x@W1l (fp16, for edge gather)
__device__ float  g_y1r[N_NODES * 128];    // x@W1r (fp32)
__device__ __half g_agg1[N_NODES * 128];   // fp16 edge-sum accumulator
__device__ float  g_cnt[N_NODES];
__device__ __half g_y2l[N_NODES * 32];     // h1@W2l (fp16)
__device__ float  g_y2r[N_NODES * 32];     // h1@W2r (fp32)
__device__ __half g_agg2[N_NODES * 32];    // fp16 edge-sum accumulator
__device__ float  g_gsum[N_GRAPHS * 32];
__device__ float  g_gcnt[N_GRAPHS];

// ============== setup: zero accumulators + weight conversion ===============
__global__ void setup_kernel(const float* __restrict__ W1l, const float* __restrict__ W1r,
                             const float* __restrict__ W2l, const float* __restrict__ W2r) {
    size_t i = (size_t)blockIdx.x * blockDim.x + threadIdx.x;
    size_t stride = (size_t)gridDim.x * blockDim.x;
    for (size_t k = i; k < (size_t)N_NODES * 64; k += stride) ((uint32_t*)g_agg1)[k] = 0u;
    for (size_t k = i; k < (size_t)N_NODES * 16; k += stride) ((uint32_t*)g_agg2)[k] = 0u;
    for (size_t k = i; k < (size_t)N_NODES;      k += stride) g_cnt[k]  = 0.f;
    for (size_t k = i; k < (size_t)N_GRAPHS * 32; k += stride) g_gsum[k] = 0.f;
    for (size_t k = i; k < (size_t)N_GRAPHS;      k += stride) g_gcnt[k] = 0.f;
    for (size_t idx = i; idx < 256 * 512; idx += stride) {
        int n = (int)(idx >> 9), k = (int)(idx & 511);
        float v = (n < 128) ? W1l[k * 128 + n] : W1r[k * 128 + (n - 128)];
        g_w1[idx] = __float2half_rn(v);
    }
    for (size_t idx = i; idx < 64 * 128; idx += stride) {
        int n = (int)(idx >> 7), k = (int)(idx & 127);
        float v = (n < 32) ? W2l[k * 32 + n] : W2r[k * 32 + (n - 32)];
        g_w2[idx] = __float2half_rn(v);
    }
}

// ============================ helpers ======================================
__device__ __forceinline__ uint32_t su32(const void* p) {
    return (uint32_t)__cvta_generic_to_shared(p);
}
__device__ __forceinline__ uint32_t pack_h2(__half a, __half b) {
    __half2 t = __halves2half2(a, b);
    return *(uint32_t*)&t;
}
__device__ __forceinline__ uint2 cvt4h(float4 v) {
    return make_uint2(pack_h2(__float2half_rn(v.x), __float2half_rn(v.y)),
                      pack_h2(__float2half_rn(v.z), __float2half_rn(v.w)));
}
__device__ __forceinline__ void mma16816h(float* c, const uint32_t* a, const uint32_t* b) {
    asm volatile(
        "mma.sync.aligned.m16n8k16.row.col.f32.f16.f16.f32 "
        "{%0,%1,%2,%3}, {%4,%5,%6,%7}, {%8,%9}, {%0,%1,%2,%3};"
        : "+f"(c[0]), "+f"(c[1]), "+f"(c[2]), "+f"(c[3])
        : "r"(a[0]), "r"(a[1]), "r"(a[2]), "r"(a[3]), "r"(b[0]), "r"(b[1]));
}
__device__ __forceinline__ void ldsm4(uint32_t* r, uint32_t addr) {
    asm volatile("ldmatrix.sync.aligned.m8n8.x4.shared.b16 {%0,%1,%2,%3}, [%4];"
                 : "=r"(r[0]), "=r"(r[1]), "=r"(r[2]), "=r"(r[3]) : "r"(addr));
}
__device__ __forceinline__ void red_h8(__half* p, uint4 v) {
    asm volatile("red.global.add.noftz.v4.f16x2 [%0], {%1,%2,%3,%4};"
                 :: "l"(p), "r"(v.x), "r"(v.y), "r"(v.z), "r"(v.w) : "memory");
}

// ===== GEMM1: [y1l|y1r] = x[M,512] @ W1^T  (fp16, fused convert, BK=64) ====
// 512 threads, CTA tile 128(M) x 256(N), BK=64, 2-stage LDG->reg(cvt)->STS.
#define G1_ROW 144
#define G1_STAGE 55296
#define SM_G1 (2 * G1_STAGE)

__global__ __launch_bounds__(512) void gemm1_mma(const float* __restrict__ x, int M) {
    extern __shared__ char smem[];
    const uint32_t sb = su32(smem);
    const int tid  = threadIdx.x;
    const int lane = tid & 31, wid = tid >> 5;
    const int wm = (wid & 3) * 32;
    const int wn = (wid >> 2) * 64;
    const int rowBase = blockIdx.x * 128;

    float acc[2][8][4];
#pragma unroll
    for (int i = 0; i < 2; i++)
#pragma unroll
        for (int j = 0; j < 8; j++)
#pragma unroll
            for (int q = 0; q < 4; q++) acc[i][j][q] = 0.f;

    const int g4 = lane & 3, gID = lane >> 2;
    const int sel = lane >> 3;
    const uint32_t rowInSel = (uint32_t)((sel & 1) * 8 + (lane & 7));
    const uint32_t colSel = (uint32_t)((sel >> 1) * 16);
    const uint32_t aOff = (wm + rowInSel) * G1_ROW + colSel;
    const uint32_t bOff = 18432 + (wn + rowInSel) * G1_ROW + colSel;

    const int arow = tid >> 2, aq = tid & 3;
    const int gra = rowBase + arow;
    const bool av = (gra < M);
    const size_t agi = (size_t)(av ? gra : 0) * 512 + aq * 16;
    const uint32_t sAo = arow * G1_ROW + aq * 32;
    const uint32_t bRow0 = tid >> 3, bQ = (uint32_t)(tid & 7);
    const size_t bgiBase = (size_t)bRow0 * 512 + bQ * 8;
    const uint32_t sBoBase = 18432 + bRow0 * G1_ROW + bQ * 16;

    float4 ra[4];
    uint4 rb[4];
    const float4 zf4 = make_float4(0.f, 0.f, 0.f, 0.f);

    auto loadRegs = [&](int kt) {
#pragma unroll
        for (int p = 0; p < 4; p++)
            ra[p] = av ? *(const float4*)(x + agi + kt + p * 4) : zf4;
#pragma unroll
        for (int p = 0; p < 4; p++)
            rb[p] = *(const uint4*)(g_w1 + bgiBase + (size_t)p * 64 * 512 + kt);
    };
    auto storeStage = [&](int s) {
        char* st = smem + s * G1_STAGE;
        uint2 h0 = cvt4h(ra[0]), h1 = cvt4h(ra[1]);
        *(uint4*)(st + sAo)      = make_uint4(h0.x, h0.y, h1.x, h1.y);
        h0 = cvt4h(ra[2]); h1 = cvt4h(ra[3]);
        *(uint4*)(st + sAo + 16) = make_uint4(h0.x, h0.y, h1.x, h1.y);
#pragma unroll
        for (int p = 0; p < 4; p++)
            *(uint4*)(st + sBoBase + p * (64 * G1_ROW)) = rb[p];
    };

    loadRegs(0);
    storeStage(0);
    __syncthreads();

    for (int it = 0; it < 8; it++) {
        const int s = it & 1;
        if (it < 7) loadRegs((it + 1) * 64);

        const uint32_t Ab = sb + s * G1_STAGE;
#pragma unroll
        for (int kk2 = 0; kk2 < 4; kk2++) {
            uint32_t a[2][4];
            ldsm4(a[0], Ab + aOff + kk2 * 32);
            ldsm4(a[1], Ab + aOff + 2304 + kk2 * 32);
#pragma unroll
            for (int ntp = 0; ntp < 4; ntp++) {
                uint32_t b[4];
                ldsm4(b, Ab + bOff + ntp * 2304 + kk2 * 32);
                uint32_t b0[2] = {b[0], b[2]};
                uint32_t b1[2] = {b[1], b[3]};
                mma16816h(acc[0][2 * ntp],     a[0], b0);
                mma16816h(acc[1][2 * ntp],     a[1], b0);
                mma16816h(acc[0][2 * ntp + 1], a[0], b1);
                mma16816h(acc[1][2 * ntp + 1], a[1], b1);
            }
        }
        if (it < 7) storeStage(s ^ 1);
        __syncthreads();
    }

    // epilogue: cols < 128 -> y1l fp16 ; cols >= 128 -> y1r fp32
#pragma unroll
    for (int mt = 0; mt < 2; mt++) {
        int r0 = rowBase + wm + mt * 16 + gID;
#pragma unroll
        for (int nt = 0; nt < 8; nt++) {
            int cc = wn + nt * 8 + g4 * 2;
            if (wn < 128) {
                uint32_t p0 = pack_h2(__float2half_rn(acc[mt][nt][0]),
                                      __float2half_rn(acc[mt][nt][1]));
                uint32_t p1 = pack_h2(__float2half_rn(acc[mt][nt][2]),
                                      __float2half_rn(acc[mt][nt][3]));
                if (r0 < M)     *(uint32_t*)(g_y1l + (size_t)r0 * 128 + cc) = p0;
                if (r0 + 8 < M) *(uint32_t*)(g_y1l + (size_t)(r0 + 8) * 128 + cc) = p1;
            } else {
                int cr = cc - 128;
                if (r0 < M)
                    *(float2*)(g_y1r + (size_t)r0 * 128 + cr) =
                        make_float2(acc[mt][nt][0], acc[mt][nt][1]);
                if (r0 + 8 < M)
                    *(float2*)(g_y1r + (size_t)(r0 + 8) * 128 + cr) =
                        make_float2(acc[mt][nt][2], acc[mt][nt][3]);
            }
        }
    }
}

// ===== GEMM2 (fused SAGE epilogue, 2-stage register-prefetch pipeline) =====
// 256 threads, tile 128(M) x 64(N), BK=32, 4 iterations, one sync/iter.
__global__ __launch_bounds__(256) void gemm2_mma(const float* __restrict__ b1l, int M) {
    __shared__ __half sA[2][128][40], sB[2][64][40];

    const int tid  = threadIdx.x;
    const int lane = tid & 31, wid = tid >> 5;
    const int wm = (wid & 3) * 32;
    const int wn = (wid >> 2) * 32;
    const int rowBase = blockIdx.x * 128;

    float acc[2][4][4];
#pragma unroll
    for (int i = 0; i < 2; i++)
#pragma unroll
        for (int j = 0; j < 4; j++)
#pragma unroll
            for (int q = 0; q < 4; q++) acc[i][j][q] = 0.f;

    const int g4 = lane & 3, gID = lane >> 2;
    const int sel = lane >> 3;
    const uint32_t rowInSel = (uint32_t)((sel & 1) * 8 + (lane & 7));
    const uint32_t colSel = (uint32_t)((sel >> 1) * 16);
    const uint32_t aOff = (wm + rowInSel) * 80 + colSel;
    const uint32_t bOff = (wn + rowInSel) * 80 + colSel;
    const uint32_t aB0 = su32(sA), bB0 = su32(sB);

    const int arow0 = tid >> 2, aq = tid & 3;
    const int gr0 = rowBase + arow0, gr1 = gr0 + 64;
    const bool av0 = (gr0 < M), av1 = (gr1 < M);
    const float inv0 = av0 ? 1.0f / fmaxf(g_cnt[gr0], 1.0f) : 0.f;
    const float inv1 = av1 ? 1.0f / fmaxf(g_cnt[gr1], 1.0f) : 0.f;

    // prefetch registers: per row-half {agg(uint4), y1r(2xfloat4)}, bias, B
    uint4  pagg[2];
    float4 pr[2][2];
    float4 pbb[2];
    uint4  pwb;
    const int brow = tid >> 2, bq = tid & 3;

    auto loadRegs = [&](int kt) {
        const int kc = kt + aq * 8;
        pbb[0] = *(const float4*)(b1l + kc);
        pbb[1] = *(const float4*)(b1l + kc + 4);
#pragma unroll
        for (int p = 0; p < 2; p++) {
            const int gr = p ? gr1 : gr0;
            const bool av = p ? av1 : av0;
            if (av) {
                pagg[p]  = *(const uint4*)(g_agg1 + (size_t)gr * 128 + kc);
                pr[p][0] = *(const float4*)(g_y1r + (size_t)gr * 128 + kc);
                pr[p][1] = *(const float4*)(g_y1r + (size_t)gr * 128 + kc + 4);
            } else {
                pagg[p] = make_uint4(0, 0, 0, 0);
                pr[p][0] = pr[p][1] = make_float4(0.f, 0.f, 0.f, 0.f);
            }
        }
        pwb = *(const uint4*)(g_w2 + (size_t)brow * 128 + kt + bq * 8);
    };
    auto storeStage = [&](int s) {
#pragma unroll
        for (int p = 0; p < 2; p++) {
            const bool av = p ? av1 : av0;
            const float inv = p ? inv1 : inv0;
            uint4 packed = make_uint4(0, 0, 0, 0);
            if (av) {
                const __half2* ah = (const __half2*)&pagg[p];
                float2 a0 = __half22float2(ah[0]), a1 = __half22float2(ah[1]);
                float2 a2 = __half22float2(ah[2]), a3 = __half22float2(ah[3]);
                float4 o0, o1;
                o0.x = fmaxf(a0.x * inv + pbb[0].x + pr[p][0].x, 0.f);
                o0.y = fmaxf(a0.y * inv + pbb[0].y + pr[p][0].y, 0.f);
                o0.z = fmaxf(a1.x * inv + pbb[0].z + pr[p][0].z, 0.f);
                o0.w = fmaxf(a1.y * inv + pbb[0].w + pr[p][0].w, 0.f);
                o1.x = fmaxf(a2.x * inv + pbb[1].x + pr[p][1].x, 0.f);
                o1.y = fmaxf(a2.y * inv + pbb[1].y + pr[p][1].y, 0.f);
                o1.z = fmaxf(a3.x * inv + pbb[1].z + pr[p][1].z, 0.f);
                o1.w = fmaxf(a3.y * inv + pbb[1].w + pr[p][1].w, 0.f);
                uint2 h0 = cvt4h(o0), h1 = cvt4h(o1);
                packed = make_uint4(h0.x, h0.y, h1.x, h1.y);
            }
            *(uint4*)&sA[s][arow0 + p * 64][aq * 8] = packed;
        }
        *(uint4*)&sB[s][brow][bq * 8] = pwb;
    };

    loadRegs(0);
    storeStage(0);
    __syncthreads();

    for (int it = 0; it < 4; it++) {
        const int s = it & 1;
        if (it < 3) loadRegs((it + 1) * 32);

        const uint32_t aB = aB0 + (uint32_t)s * 10240;
        const uint32_t bB = bB0 + (uint32_t)s * 5120;
#pragma unroll
        for (int kk2 = 0; kk2 < 2; kk2++) {
            uint32_t a[2][4];
            ldsm4(a[0], aB + aOff + kk2 * 32);
            ldsm4(a[1], aB + aOff + 1280 + kk2 * 32);
#pragma unroll
            for (int ntp = 0; ntp < 2; ntp++) {
                uint32_t b[4];
                ldsm4(b, bB + bOff + ntp * 1280 + kk2 * 32);
                uint32_t b0[2] = {b[0], b[2]};
                uint32_t b1[2] = {b[1], b[3]};
                mma16816h(acc[0][2 * ntp],     a[0], b0);
                mma16816h(acc[1][2 * ntp],     a[1], b0);
                mma16816h(acc[0][2 * ntp + 1], a[0], b1);
                mma16816h(acc[1][2 * ntp + 1], a[1], b1);
            }
        }
        if (it < 3) storeStage(s ^ 1);
        __syncthreads();
    }

    // epilogue: cols < 32 -> y2l fp16 ; cols >= 32 -> y2r fp32
#pragma unroll
    for (int mt = 0; mt < 2; mt++) {
        int r0 = rowBase + wm + mt * 16 + gID;
#pragma unroll
        for (int nt = 0; nt < 4; nt++) {
            int cc = wn + nt * 8 + g4 * 2;
            if (cc < 32) {
                uint32_t p0 = pack_h2(__float2half_rn(acc[mt][nt][0]),
                                      __float2half_rn(acc[mt][nt][1]));
                uint32_t p1 = pack_h2(__float2half_rn(acc[mt][nt][2]),
                                      __float2half_rn(acc[mt][nt][3]));
                if (r0 < M)     *(uint32_t*)(g_y2l + (size_t)r0 * 32 + cc) = p0;
                if (r0 + 8 < M) *(uint32_t*)(g_y2l + (size_t)(r0 + 8) * 32 + cc) = p1;
            } else {
                int cr = cc - 32;
                if (r0 < M)
                    *(float2*)(g_y2r + (size_t)r0 * 32 + cr) =
                        make_float2(acc[mt][nt][0], acc[mt][nt][1]);
                if (r0 + 8 < M)
                    *(float2*)(g_y2r + (size_t)(r0 + 8) * 32 + cr) =
                        make_float2(acc[mt][nt][2], acc[mt][nt][3]);
            }
        }
    }
}

// -------- edge aggregation, layer 1 (128 fp16 feats, 16 threads/edge) ------
__global__ void edge_agg1(const int* __restrict__ ei) {
    int gtid = blockIdx.x * blockDim.x + threadIdx.x;
    int e = gtid >> 4;
    int lane = gtid & 15;
    if (e >= N_EDGES) return;
    int src = ei[e];
    int dst = ei[N_EDGES + e];
    uint4 v = *(const uint4*)(g_y1l + (size_t)src * 128 + lane * 8);
    red_h8(g_agg1 + (size_t)dst * 128 + lane * 8, v);
    if (lane == 0) atomicAdd(&g_cnt[dst], 1.0f);
}

// -------- edge aggregation, layer 2 (32 fp16 feats, 4 threads/edge) --------
__global__ void edge_agg2(const int* __restrict__ ei) {
    int gtid = blockIdx.x * blockDim.x + threadIdx.x;
    int e = gtid >> 2;
    int lane = gtid & 3;
    if (e >= N_EDGES) return;
    int src = ei[e];
    int dst = ei[N_EDGES + e];
    uint4 v = *(const uint4*)(g_y2l + (size_t)src * 32 + lane * 8);
    red_h8(g_agg2 + (size_t)dst * 32 + lane * 8, v);
}

// ---------------- fused layer-2 epilogue + per-graph mean pool --------------
__global__ void pool_kernel(const int* __restrict__ batch, const float* __restrict__ b2l) {
    int f = threadIdx.x;           // 32
    int yid = threadIdx.y;         // 8
    int n0 = blockIdx.x * 512 + yid;
    float b = b2l[f];
    float acc = 0.f, cacc = 0.f;
    int cur = -1;
    for (int it = 0; it < 64; it++) {
        int n = n0 + it * 8;
        if (n < N_NODES) {
            int g = batch[n];
            if (g != cur) {
                if (cur >= 0) {
                    atomicAdd(&g_gsum[cur * 32 + f], acc);
                    if (f == 0) atomicAdd(&g_gcnt[cur], cacc);
                }
                cur = g; acc = 0.f; cacc = 0.f;
            }
            float inv = 1.0f / fmaxf(g_cnt[n], 1.0f);
            float v = __half2float(g_agg2[(size_t)n * 32 + f]) * inv + b +
                      g_y2r[(size_t)n * 32 + f];
            acc += fmaxf(v, 0.f);
            cacc += 1.f;
        }
    }
    if (cur >= 0) {
        atomicAdd(&g_gsum[cur * 32 + f], acc);
        if (f == 0) atomicAdd(&g_gcnt[cur], cacc);
    }
}

// ---------------- final tiny MLP (encoder head + decoder) ------------------
__global__ void mlp_kernel(const float* __restrict__ Wl1, const float* __restrict__ bl1,
                           const float* __restrict__ Wl2, const float* __restrict__ bl2,
                           const float* __restrict__ Wd1, const float* __restrict__ bd1,
                           const float* __restrict__ Wd2, const float* __restrict__ bd2,
                           const float* __restrict__ Wd3, const float* __restrict__ bd3,
                           float* __restrict__ out) {
    __shared__ float sWl1[1024], sWl2[512], sWd1[512], sWd2[1024], sWd3[1600];
    __shared__ float sbl1[32], sbl2[16], sbd1[32], sbd2[32], sbd3[50];
    int t = threadIdx.x;           // 64
    for (int i = t; i < 1024; i += 64) sWl1[i] = Wl1[i];
    for (int i = t; i < 512;  i += 64) sWl2[i] = Wl2[i];
    for (int i = t; i < 512;  i += 64) sWd1[i] = Wd1[i];
    for (int i = t; i < 1024; i += 64) sWd2[i] = Wd2[i];
    for (int i = t; i < 1600; i += 64) sWd3[i] = Wd3[i];
    if (t < 32) sbl1[t] = bl1[t];
    if (t < 16) sbl2[t] = bl2[t];
    if (t < 32) sbd1[t] = bd1[t];
    if (t < 32) sbd2[t] = bd2[t];
    for (int i = t; i < 50; i += 64) sbd3[i] = bd3[i];
    __syncthreads();
    if (t >= N_GRAPHS) return;

    float gv[32];
    float inv = 1.0f / fmaxf(g_gcnt[t], 1.0f);
#pragma unroll
    for (int i = 0; i < 32; i++) gv[i] = g_gsum[t * 32 + i] * inv;

    float a[32];
#pragma unroll
    for (int j = 0; j < 32; j++) {
        float s = sbl1[j];
#pragma unroll
        for (int i = 0; i < 32; i++) s = fmaf(gv[i], sWl1[i * 32 + j], s);
        a[j] = fmaxf(s, 0.f);
    }
    float enc[16];
#pragma unroll
    for (int j = 0; j < 16; j++) {
        float s = sbl2[j];
#pragma unroll
        for (int i = 0; i < 32; i++) s = fmaf(a[i], sWl2[i * 16 + j], s);
        enc[j] = s > 0.f ? s : 0.1f * s;
    }
#pragma unroll
    for (int j = 0; j < 16; j++) out[t * 16 + j] = enc[j];

    float z1[32];
#pragma unroll
    for (int j = 0; j < 32; j++) {
        float s = sbd1[j];
#pragma unroll
        for (int i = 0; i < 16; i++) s = fmaf(enc[i], sWd1[i * 32 + j], s);
        z1[j] = s > 0.f ? s : 0.1f * s;
    }
    float z2[32];
#pragma unroll
    for (int j = 0; j < 32; j++) {
        float s = sbd2[j];
#pragma unroll
        for (int i = 0; i < 32; i++) s = fmaf(z1[i], sWd2[i * 32 + j], s);
        z2[j] = s > 0.f ? s : 0.1f * s;
    }
#pragma unroll
    for (int j = 0; j < 50; j++) {
        float s = sbd3[j];
#pragma unroll
        for (int i = 0; i < 32; i++) s = fmaf(z2[i], sWd3[i * 50 + j], s);
        out[1024 + t * 50 + j] = s;
    }
}

// ---------------- launch ----------------------------------------------------
extern "C" void kernel_launch(void* const* d_in, const int* in_sizes, int n_in,
                              void* d_out, int out_size) {
    const float* x   = (const float*)d_in[0];
    const int*   ei  = (const int*)d_in[1];
    const int*   bat = (const int*)d_in[2];
    const float* W1l = (const float*)d_in[3];
    const float* b1l = (const float*)d_in[4];
    const float* W1r = (const float*)d_in[5];
    const float* W2l = (const float*)d_in[6];
    const float* b2l = (const float*)d_in[7];
    const float* W2r = (const float*)d_in[8];
    const float* Wl1 = (const float*)d_in[9];
    const float* bl1 = (const float*)d_in[10];
    const float* Wl2 = (const float*)d_in[11];
    const float* bl2 = (const float*)d_in[12];
    const float* Wd1 = (const float*)d_in[13];
    const float* bd1 = (const float*)d_in[14];
    const float* Wd2 = (const float*)d_in[15];
    const float* bd2 = (const float*)d_in[16];
    const float* Wd3 = (const float*)d_in[17];
    const float* bd3 = (const float*)d_in[18];
    float* out = (float*)d_out;

    static bool attr_set = false;
    if (!attr_set) {
        cudaFuncSetAttribute(gemm1_mma, cudaFuncAttributeMaxDynamicSharedMemorySize, SM_G1);
        attr_set = true;
    }

    setup_kernel<<<592, 256>>>(W1l, W1r, W2l, W2r);

    // GEMM1 (tensor pipe, fp16, fused convert, BK=64, 2-stage)
    gemm1_mma<<<(N_NODES + 127) / 128, 512, SM_G1>>>(x, N_NODES);

    edge_agg1<<<25000, 256>>>(ei);   // fp16 v4 reductions, 16 thr/edge

    // GEMM2 (tensor pipe, fused SAGE epilogue, 2-stage prefetch)
    gemm2_mma<<<(N_NODES + 127) / 128, 256>>>(b1l, N_NODES);

    edge_agg2<<<6250, 256>>>(ei);    // fp16 v4 reductions, 4 thr/edge

    {
        dim3 blk(32, 8);
        pool_kernel<<<(N_NODES + 511) / 512, blk>>>(bat, b2l);
    }

    mlp_kernel<<<1, 64>>>(Wl1, bl1, Wl2, bl2, Wd1, bd1, Wd2, bd2, Wd3, bd3, out);
}

// round 14
// speedup vs baseline: 1.1845x; 1.1354x over previous
#include <cuda_runtime.h>
#include <cuda_fp16.h>
#include <cstdint>

#define N_NODES  50000
#define N_EDGES  400000
#define N_GRAPHS 64

// ============================ device scratch ===============================
__device__ __half g_w1[256 * 512];         // [W1l|W1r]^T fp16  [256 n][512 k]
__device__ __half g_w2[64 * 128];          // [W2l|W2r]^T fp16  [64 n][128 k]
__device__ __half g_y1l[N_NODES * 128];    // x@W1l (fp16, for edge gather)
__device__ float  g_y1r[N_NODES * 128];    // x@W1r (fp32)
__device__ __half g_agg1[N_NODES * 128];   // fp16 edge-sum accumulator
__device__ float  g_cnt[N_NODES];
__device__ __half g_y2l[N_NODES * 32];     // h1@W2l (fp16)
__device__ float  g_y2r[N_NODES * 32];     // h1@W2r (fp32)
__device__ __half g_agg2[N_NODES * 32];    // fp16 edge-sum accumulator
__device__ float  g_gsum[N_GRAPHS * 32];
__device__ float  g_gcnt[N_GRAPHS];
__device__ int    g_ticket;

// ============== setup: zero accumulators + weight conversion ===============
__global__ void setup_kernel(const float* __restrict__ W1l, const float* __restrict__ W1r,
                             const float* __restrict__ W2l, const float* __restrict__ W2r) {
    size_t i = (size_t)blockIdx.x * blockDim.x + threadIdx.x;
    size_t stride = (size_t)gridDim.x * blockDim.x;
    if (i == 0) g_ticket = 0;
    for (size_t k = i; k < (size_t)N_NODES * 64; k += stride) ((uint32_t*)g_agg1)[k] = 0u;
    for (size_t k = i; k < (size_t)N_NODES * 16; k += stride) ((uint32_t*)g_agg2)[k] = 0u;
    for (size_t k = i; k < (size_t)N_NODES;      k += stride) g_cnt[k]  = 0.f;
    for (size_t k = i; k < (size_t)N_GRAPHS * 32; k += stride) g_gsum[k] = 0.f;
    for (size_t k = i; k < (size_t)N_GRAPHS;      k += stride) g_gcnt[k] = 0.f;
    for (size_t idx = i; idx < 256 * 512; idx += stride) {
        int n = (int)(idx >> 9), k = (int)(idx & 511);
        float v = (n < 128) ? W1l[k * 128 + n] : W1r[k * 128 + (n - 128)];
        g_w1[idx] = __float2half_rn(v);
    }
    for (size_t idx = i; idx < 64 * 128; idx += stride) {
        int n = (int)(idx >> 7), k = (int)(idx & 127);
        float v = (n < 32) ? W2l[k * 32 + n] : W2r[k * 32 + (n - 32)];
        g_w2[idx] = __float2half_rn(v);
    }
}

// ============================ helpers ======================================
__device__ __forceinline__ uint32_t su32(const void* p) {
    return (uint32_t)__cvta_generic_to_shared(p);
}
__device__ __forceinline__ uint32_t pack_h2(__half a, __half b) {
    __half2 t = __halves2half2(a, b);
    return *(uint32_t*)&t;
}
__device__ __forceinline__ uint2 cvt4h(float4 v) {
    return make_uint2(pack_h2(__float2half_rn(v.x), __float2half_rn(v.y)),
                      pack_h2(__float2half_rn(v.z), __float2half_rn(v.w)));
}
__device__ __forceinline__ void mma16816h(float* c, const uint32_t* a, const uint32_t* b) {
    asm volatile(
        "mma.sync.aligned.m16n8k16.row.col.f32.f16.f16.f32 "
        "{%0,%1,%2,%3}, {%4,%5,%6,%7}, {%8,%9}, {%0,%1,%2,%3};"
        : "+f"(c[0]), "+f"(c[1]), "+f"(c[2]), "+f"(c[3])
        : "r"(a[0]), "r"(a[1]), "r"(a[2]), "r"(a[3]), "r"(b[0]), "r"(b[1]));
}
__device__ __forceinline__ void ldsm4(uint32_t* r, uint32_t addr) {
    asm volatile("ldmatrix.sync.aligned.m8n8.x4.shared.b16 {%0,%1,%2,%3}, [%4];"
                 : "=r"(r[0]), "=r"(r[1]), "=r"(r[2]), "=r"(r[3]) : "r"(addr));
}
__device__ __forceinline__ void red_h8(__half* p, uint4 v) {
    asm volatile("red.global.add.noftz.v4.f16x2 [%0], {%1,%2,%3,%4};"
                 :: "l"(p), "r"(v.x), "r"(v.y), "r"(v.z), "r"(v.w) : "memory");
}

// ===== GEMM1: [y1l|y1r] = x[M,512] @ W1^T  (fp16, fused convert, BK=64) ====
// 512 threads, CTA tile 128(M) x 256(N), BK=64, 2-stage, mid-loop store.
#define G1_ROW 144
#define G1_STAGE 55296
#define SM_G1 (2 * G1_STAGE)

__global__ __launch_bounds__(512) void gemm1_mma(const float* __restrict__ x, int M) {
    extern __shared__ char smem[];
    const uint32_t sb = su32(smem);
    const int tid  = threadIdx.x;
    const int lane = tid & 31, wid = tid >> 5;
    const int wm = (wid & 3) * 32;
    const int wn = (wid >> 2) * 64;
    const int rowBase = blockIdx.x * 128;

    float acc[2][8][4];
#pragma unroll
    for (int i = 0; i < 2; i++)
#pragma unroll
        for (int j = 0; j < 8; j++)
#pragma unroll
            for (int q = 0; q < 4; q++) acc[i][j][q] = 0.f;

    const int g4 = lane & 3, gID = lane >> 2;
    const int sel = lane >> 3;
    const uint32_t rowInSel = (uint32_t)((sel & 1) * 8 + (lane & 7));
    const uint32_t colSel = (uint32_t)((sel >> 1) * 16);
    const uint32_t aOff = (wm + rowInSel) * G1_ROW + colSel;
    const uint32_t bOff = 18432 + (wn + rowInSel) * G1_ROW + colSel;

    const int arow = tid >> 2, aq = tid & 3;
    const int gra = rowBase + arow;
    const bool av = (gra < M);
    const size_t agi = (size_t)(av ? gra : 0) * 512 + aq * 16;
    const uint32_t sAo = arow * G1_ROW + aq * 32;
    const uint32_t bRow0 = tid >> 3, bQ = (uint32_t)(tid & 7);
    const size_t bgiBase = (size_t)bRow0 * 512 + bQ * 8;
    const uint32_t sBoBase = 18432 + bRow0 * G1_ROW + bQ * 16;

    float4 ra[4];
    uint4 rb[4];
    const float4 zf4 = make_float4(0.f, 0.f, 0.f, 0.f);

    auto loadRegs = [&](int kt) {
#pragma unroll
        for (int p = 0; p < 4; p++)
            ra[p] = av ? *(const float4*)(x + agi + kt + p * 4) : zf4;
#pragma unroll
        for (int p = 0; p < 4; p++)
            rb[p] = *(const uint4*)(g_w1 + bgiBase + (size_t)p * 64 * 512 + kt);
    };
    auto storeStage = [&](int s) {
        char* st = smem + s * G1_STAGE;
        uint2 h0 = cvt4h(ra[0]), h1 = cvt4h(ra[1]);
        *(uint4*)(st + sAo)      = make_uint4(h0.x, h0.y, h1.x, h1.y);
        h0 = cvt4h(ra[2]); h1 = cvt4h(ra[3]);
        *(uint4*)(st + sAo + 16) = make_uint4(h0.x, h0.y, h1.x, h1.y);
#pragma unroll
        for (int p = 0; p < 4; p++)
            *(uint4*)(st + sBoBase + p * (64 * G1_ROW)) = rb[p];
    };

    loadRegs(0);
    storeStage(0);
    __syncthreads();

    for (int it = 0; it < 8; it++) {
        const int s = it & 1;
        if (it < 7) loadRegs((it + 1) * 64);

        const uint32_t Ab = sb + s * G1_STAGE;
        // first half of MMA (kk2 = 0,1)
#pragma unroll
        for (int kk2 = 0; kk2 < 2; kk2++) {
            uint32_t a[2][4];
            ldsm4(a[0], Ab + aOff + kk2 * 32);
            ldsm4(a[1], Ab + aOff + 2304 + kk2 * 32);
#pragma unroll
            for (int ntp = 0; ntp < 4; ntp++) {
                uint32_t b[4];
                ldsm4(b, Ab + bOff + ntp * 2304 + kk2 * 32);
                uint32_t b0[2] = {b[0], b[2]};
                uint32_t b1[2] = {b[1], b[3]};
                mma16816h(acc[0][2 * ntp],     a[0], b0);
                mma16816h(acc[1][2 * ntp],     a[1], b0);
                mma16816h(acc[0][2 * ntp + 1], a[0], b1);
                mma16816h(acc[1][2 * ntp + 1], a[1], b1);
            }
        }
        // store next stage mid-loop (STS completes under second MMA half)
        if (it < 7) storeStage(s ^ 1);
        // second half of MMA (kk2 = 2,3)
#pragma unroll
        for (int kk2 = 2; kk2 < 4; kk2++) {
            uint32_t a[2][4];
            ldsm4(a[0], Ab + aOff + kk2 * 32);
            ldsm4(a[1], Ab + aOff + 2304 + kk2 * 32);
#pragma unroll
            for (int ntp = 0; ntp < 4; ntp++) {
                uint32_t b[4];
                ldsm4(b, Ab + bOff + ntp * 2304 + kk2 * 32);
                uint32_t b0[2] = {b[0], b[2]};
                uint32_t b1[2] = {b[1], b[3]};
                mma16816h(acc[0][2 * ntp],     a[0], b0);
                mma16816h(acc[1][2 * ntp],     a[1], b0);
                mma16816h(acc[0][2 * ntp + 1], a[0], b1);
                mma16816h(acc[1][2 * ntp + 1], a[1], b1);
            }
        }
        __syncthreads();
    }

    // epilogue: cols < 128 -> y1l fp16 ; cols >= 128 -> y1r fp32
#pragma unroll
    for (int mt = 0; mt < 2; mt++) {
        int r0 = rowBase + wm + mt * 16 + gID;
#pragma unroll
        for (int nt = 0; nt < 8; nt++) {
            int cc = wn + nt * 8 + g4 * 2;
            if (wn < 128) {
                uint32_t p0 = pack_h2(__float2half_rn(acc[mt][nt][0]),
                                      __float2half_rn(acc[mt][nt][1]));
                uint32_t p1 = pack_h2(__float2half_rn(acc[mt][nt][2]),
                                      __float2half_rn(acc[mt][nt][3]));
                if (r0 < M)     *(uint32_t*)(g_y1l + (size_t)r0 * 128 + cc) = p0;
                if (r0 + 8 < M) *(uint32_t*)(g_y1l + (size_t)(r0 + 8) * 128 + cc) = p1;
            } else {
                int cr = cc - 128;
                if (r0 < M)
                    *(float2*)(g_y1r + (size_t)r0 * 128 + cr) =
                        make_float2(acc[mt][nt][0], acc[mt][nt][1]);
                if (r0 + 8 < M)
                    *(float2*)(g_y1r + (size_t)(r0 + 8) * 128 + cr) =
                        make_float2(acc[mt][nt][2], acc[mt][nt][3]);
            }
        }
    }
}

// ===== GEMM2 (fused SAGE epilogue, 2-stage register-prefetch pipeline) =====
__global__ __launch_bounds__(256) void gemm2_mma(const float* __restrict__ b1l, int M) {
    __shared__ __half sA[2][128][40], sB[2][64][40];

    const int tid  = threadIdx.x;
    const int lane = tid & 31, wid = tid >> 5;
    const int wm = (wid & 3) * 32;
    const int wn = (wid >> 2) * 32;
    const int rowBase = blockIdx.x * 128;

    float acc[2][4][4];
#pragma unroll
    for (int i = 0; i < 2; i++)
#pragma unroll
        for (int j = 0; j < 4; j++)
#pragma unroll
            for (int q = 0; q < 4; q++) acc[i][j][q] = 0.f;

    const int g4 = lane & 3, gID = lane >> 2;
    const int sel = lane >> 3;
    const uint32_t rowInSel = (uint32_t)((sel & 1) * 8 + (lane & 7));
    const uint32_t colSel = (uint32_t)((sel >> 1) * 16);
    const uint32_t aOff = (wm + rowInSel) * 80 + colSel;
    const uint32_t bOff = (wn + rowInSel) * 80 + colSel;
    const uint32_t aB0 = su32(sA), bB0 = su32(sB);

    const int arow0 = tid >> 2, aq = tid & 3;
    const int gr0 = rowBase + arow0, gr1 = gr0 + 64;
    const bool av0 = (gr0 < M), av1 = (gr1 < M);
    const float inv0 = av0 ? 1.0f / fmaxf(g_cnt[gr0], 1.0f) : 0.f;
    const float inv1 = av1 ? 1.0f / fmaxf(g_cnt[gr1], 1.0f) : 0.f;

    uint4  pagg[2];
    float4 pr[2][2];
    float4 pbb[2];
    uint4  pwb;
    const int brow = tid >> 2, bq = tid & 3;

    auto loadRegs = [&](int kt) {
        const int kc = kt + aq * 8;
        pbb[0] = *(const float4*)(b1l + kc);
        pbb[1] = *(const float4*)(b1l + kc + 4);
#pragma unroll
        for (int p = 0; p < 2; p++) {
            const int gr = p ? gr1 : gr0;
            const bool av = p ? av1 : av0;
            if (av) {
                pagg[p]  = *(const uint4*)(g_agg1 + (size_t)gr * 128 + kc);
                pr[p][0] = *(const float4*)(g_y1r + (size_t)gr * 128 + kc);
                pr[p][1] = *(const float4*)(g_y1r + (size_t)gr * 128 + kc + 4);
            } else {
                pagg[p] = make_uint4(0, 0, 0, 0);
                pr[p][0] = pr[p][1] = make_float4(0.f, 0.f, 0.f, 0.f);
            }
        }
        pwb = *(const uint4*)(g_w2 + (size_t)brow * 128 + kt + bq * 8);
    };
    auto storeStage = [&](int s) {
#pragma unroll
        for (int p = 0; p < 2; p++) {
            const bool av = p ? av1 : av0;
            const float inv = p ? inv1 : inv0;
            uint4 packed = make_uint4(0, 0, 0, 0);
            if (av) {
                const __half2* ah = (const __half2*)&pagg[p];
                float2 a0 = __half22float2(ah[0]), a1 = __half22float2(ah[1]);
                float2 a2 = __half22float2(ah[2]), a3 = __half22float2(ah[3]);
                float4 o0, o1;
                o0.x = fmaxf(a0.x * inv + pbb[0].x + pr[p][0].x, 0.f);
                o0.y = fmaxf(a0.y * inv + pbb[0].y + pr[p][0].y, 0.f);
                o0.z = fmaxf(a1.x * inv + pbb[0].z + pr[p][0].z, 0.f);
                o0.w = fmaxf(a1.y * inv + pbb[0].w + pr[p][0].w, 0.f);
                o1.x = fmaxf(a2.x * inv + pbb[1].x + pr[p][1].x, 0.f);
                o1.y = fmaxf(a2.y * inv + pbb[1].y + pr[p][1].y, 0.f);
                o1.z = fmaxf(a3.x * inv + pbb[1].z + pr[p][1].z, 0.f);
                o1.w = fmaxf(a3.y * inv + pbb[1].w + pr[p][1].w, 0.f);
                uint2 h0 = cvt4h(o0), h1 = cvt4h(o1);
                packed = make_uint4(h0.x, h0.y, h1.x, h1.y);
            }
            *(uint4*)&sA[s][arow0 + p * 64][aq * 8] = packed;
        }
        *(uint4*)&sB[s][brow][bq * 8] = pwb;
    };

    loadRegs(0);
    storeStage(0);
    __syncthreads();

    for (int it = 0; it < 4; it++) {
        const int s = it & 1;
        if (it < 3) loadRegs((it + 1) * 32);

        const uint32_t aB = aB0 + (uint32_t)s * 10240;
        const uint32_t bB = bB0 + (uint32_t)s * 5120;
#pragma unroll
        for (int kk2 = 0; kk2 < 2; kk2++) {
            uint32_t a[2][4];
            ldsm4(a[0], aB + aOff + kk2 * 32);
            ldsm4(a[1], aB + aOff + 1280 + kk2 * 32);
#pragma unroll
            for (int ntp = 0; ntp < 2; ntp++) {
                uint32_t b[4];
                ldsm4(b, bB + bOff + ntp * 1280 + kk2 * 32);
                uint32_t b0[2] = {b[0], b[2]};
                uint32_t b1[2] = {b[1], b[3]};
                mma16816h(acc[0][2 * ntp],     a[0], b0);
                mma16816h(acc[1][2 * ntp],     a[1], b0);
                mma16816h(acc[0][2 * ntp + 1], a[0], b1);
                mma16816h(acc[1][2 * ntp + 1], a[1], b1);
            }
        }
        if (it < 3) storeStage(s ^ 1);
        __syncthreads();
    }

    // epilogue: cols < 32 -> y2l fp16 ; cols >= 32 -> y2r fp32
#pragma unroll
    for (int mt = 0; mt < 2; mt++) {
        int r0 = rowBase + wm + mt * 16 + gID;
#pragma unroll
        for (int nt = 0; nt < 4; nt++) {
            int cc = wn + nt * 8 + g4 * 2;
            if (cc < 32) {
                uint32_t p0 = pack_h2(__float2half_rn(acc[mt][nt][0]),
                                      __float2half_rn(acc[mt][nt][1]));
                uint32_t p1 = pack_h2(__float2half_rn(acc[mt][nt][2]),
                                      __float2half_rn(acc[mt][nt][3]));
                if (r0 < M)     *(uint32_t*)(g_y2l + (size_t)r0 * 32 + cc) = p0;
                if (r0 + 8 < M) *(uint32_t*)(g_y2l + (size_t)(r0 + 8) * 32 + cc) = p1;
            } else {
                int cr = cc - 32;
                if (r0 < M)
                    *(float2*)(g_y2r + (size_t)r0 * 32 + cr) =
                        make_float2(acc[mt][nt][0], acc[mt][nt][1]);
                if (r0 + 8 < M)
                    *(float2*)(g_y2r + (size_t)(r0 + 8) * 32 + cr) =
                        make_float2(acc[mt][nt][2], acc[mt][nt][3]);
            }
        }
    }
}

// -------- edge aggregation, layer 1 (128 fp16 feats, 16 threads/edge) ------
__global__ void edge_agg1(const int* __restrict__ ei) {
    int gtid = blockIdx.x * blockDim.x + threadIdx.x;
    int e = gtid >> 4;
    int lane = gtid & 15;
    if (e >= N_EDGES) return;
    int src = ei[e];
    int dst = ei[N_EDGES + e];
    uint4 v = *(const uint4*)(g_y1l + (size_t)src * 128 + lane * 8);
    red_h8(g_agg1 + (size_t)dst * 128 + lane * 8, v);
    if (lane == 0) atomicAdd(&g_cnt[dst], 1.0f);
}

// -------- edge aggregation, layer 2 (32 fp16 feats, 4 threads/edge) --------
__global__ void edge_agg2(const int* __restrict__ ei) {
    int gtid = blockIdx.x * blockDim.x + threadIdx.x;
    int e = gtid >> 2;
    int lane = gtid & 3;
    if (e >= N_EDGES) return;
    int src = ei[e];
    int dst = ei[N_EDGES + e];
    uint4 v = *(const uint4*)(g_y2l + (size_t)src * 32 + lane * 8);
    red_h8(g_agg2 + (size_t)dst * 32 + lane * 8, v);
}

// ====== fused layer-2 epilogue + per-graph mean pool + final MLP ===========
// grid 391 (128 nodes/block, 16 iters); last block (ticket) runs the MLP.
__global__ void pool_kernel(const int* __restrict__ batch, const float* __restrict__ b2l,
                            const float* __restrict__ Wl1, const float* __restrict__ bl1,
                            const float* __restrict__ Wl2, const float* __restrict__ bl2,
                            const float* __restrict__ Wd1, const float* __restrict__ bd1,
                            const float* __restrict__ Wd2, const float* __restrict__ bd2,
                            const float* __restrict__ Wd3, const float* __restrict__ bd3,
                            float* __restrict__ out) {
    __shared__ bool sLast;
    __shared__ float sWl1[1024], sWl2[512], sWd1[512], sWd2[1024], sWd3[1600];
    __shared__ float sbl1[32], sbl2[16], sbd1[32], sbd2[32], sbd3[50];

    int f = threadIdx.x;           // 32
    int yid = threadIdx.y;         // 8
    int tid = yid * 32 + f;        // 0..255
    int n0 = blockIdx.x * 128 + yid;
    float b = b2l[f];
    float acc = 0.f, cacc = 0.f;
    int cur = -1;
    for (int it = 0; it < 16; it++) {
        int n = n0 + it * 8;
        if (n < N_NODES) {
            int g = batch[n];
            if (g != cur) {
                if (cur >= 0) {
                    atomicAdd(&g_gsum[cur * 32 + f], acc);
                    if (f == 0) atomicAdd(&g_gcnt[cur], cacc);
                }
                cur = g; acc = 0.f; cacc = 0.f;
            }
            float inv = 1.0f / fmaxf(g_cnt[n], 1.0f);
            float v = __half2float(g_agg2[(size_t)n * 32 + f]) * inv + b +
                      g_y2r[(size_t)n * 32 + f];
            acc += fmaxf(v, 0.f);
            cacc += 1.f;
        }
    }
    if (cur >= 0) {
        atomicAdd(&g_gsum[cur * 32 + f], acc);
        if (f == 0) atomicAdd(&g_gcnt[cur], cacc);
    }

    // ---- last-block ticket: run the tiny MLP once all gsum flushed ----
    __threadfence();
    __syncthreads();
    if (tid == 0) {
        int v = atomicAdd(&g_ticket, 1);
        sLast = (v == (int)gridDim.x - 1);
    }
    __syncthreads();
    if (!sLast) return;

    for (int i = tid; i < 1024; i += 256) sWl1[i] = Wl1[i];
    for (int i = tid; i < 512;  i += 256) sWl2[i] = Wl2[i];
    for (int i = tid; i < 512;  i += 256) sWd1[i] = Wd1[i];
    for (int i = tid; i < 1024; i += 256) sWd2[i] = Wd2[i];
    for (int i = tid; i < 1600; i += 256) sWd3[i] = Wd3[i];
    if (tid < 32) sbl1[tid] = bl1[tid];
    if (tid < 16) sbl2[tid] = bl2[tid];
    if (tid < 32) sbd1[tid] = bd1[tid];
    if (tid < 32) sbd2[tid] = bd2[tid];
    if (tid < 50) sbd3[tid] = bd3[tid];
    __syncthreads();
    if (tid >= N_GRAPHS) return;
    int t = tid;

    float gv[32];
    float inv = 1.0f / fmaxf(g_gcnt[t], 1.0f);
#pragma unroll
    for (int i = 0; i < 32; i++) gv[i] = g_gsum[t * 32 + i] * inv;

    float a[32];
#pragma unroll
    for (int j = 0; j < 32; j++) {
        float s = sbl1[j];
#pragma unroll
        for (int i = 0; i < 32; i++) s = fmaf(gv[i], sWl1[i * 32 + j], s);
        a[j] = fmaxf(s, 0.f);
    }
    float enc[16];
#pragma unroll
    for (int j = 0; j < 16; j++) {
        float s = sbl2[j];
#pragma unroll
        for (int i = 0; i < 32; i++) s = fmaf(a[i], sWl2[i * 16 + j], s);
        enc[j] = s > 0.f ? s : 0.1f * s;
    }
#pragma unroll
    for (int j = 0; j < 16; j++) out[t * 16 + j] = enc[j];

    float z1[32];
#pragma unroll
    for (int j = 0; j < 32; j++) {
        float s = sbd1[j];
#pragma unroll
        for (int i = 0; i < 16; i++) s = fmaf(enc[i], sWd1[i * 32 + j], s);
        z1[j] = s > 0.f ? s : 0.1f * s;
    }
    float z2[32];
#pragma unroll
    for (int j = 0; j < 32; j++) {
        float s = sbd2[j];
#pragma unroll
        for (int i = 0; i < 32; i++) s = fmaf(z1[i], sWd2[i * 32 + j], s);
        z2[j] = s > 0.f ? s : 0.1f * s;
    }
#pragma unroll
    for (int j = 0; j < 50; j++) {
        float s = sbd3[j];
#pragma unroll
        for (int i = 0; i < 32; i++) s = fmaf(z2[i], sWd3[i * 50 + j], s);
        out[1024 + t * 50 + j] = s;
    }
}

// ---------------- launch ----------------------------------------------------
extern "C" void kernel_launch(void* const* d_in, const int* in_sizes, int n_in,
                              void* d_out, int out_size) {
    const float* x   = (const float*)d_in[0];
    const int*   ei  = (const int*)d_in[1];
    const int*   bat = (const int*)d_in[2];
    const float* W1l = (const float*)d_in[3];
    const float* b1l = (const float*)d_in[4];
    const float* W1r = (const float*)d_in[5];
    const float* W2l = (const float*)d_in[6];
    const float* b2l = (const float*)d_in[7];
    const float* W2r = (const float*)d_in[8];
    const float* Wl1 = (const float*)d_in[9];
    const float* bl1 = (const float*)d_in[10];
    const float* Wl2 = (const float*)d_in[11];
    const float* bl2 = (const float*)d_in[12];
    const float* Wd1 = (const float*)d_in[13];
    const float* bd1 = (const float*)d_in[14];
    const float* Wd2 = (const float*)d_in[15];
    const float* bd2 = (const float*)d_in[16];
    const float* Wd3 = (const float*)d_in[17];
    const float* bd3 = (const float*)d_in[18];
    float* out = (float*)d_out;

    static bool attr_set = false;
    if (!attr_set) {
        cudaFuncSetAttribute(gemm1_mma, cudaFuncAttributeMaxDynamicSharedMemorySize, SM_G1);
        attr_set = true;
    }

    setup_kernel<<<592, 256>>>(W1l, W1r, W2l, W2r);

    // GEMM1 (tensor pipe, fp16, fused convert, BK=64, mid-loop store)
    gemm1_mma<<<(N_NODES + 127) / 128, 512, SM_G1>>>(x, N_NODES);

    edge_agg1<<<25000, 256>>>(ei);   // fp16 v4 reductions, 16 thr/edge

    // GEMM2 (tensor pipe, fused SAGE epilogue, 2-stage prefetch)
    gemm2_mma<<<(N_NODES + 127) / 128, 256>>>(b1l, N_NODES);

    edge_agg2<<<6250, 256>>>(ei);    // fp16 v4 reductions, 4 thr/edge

    // pool + fused MLP (last-block ticket)
    {
        dim3 blk(32, 8);
        pool_kernel<<<(N_NODES + 127) / 128, blk>>>(bat, b2l,
            Wl1, bl1, Wl2, bl2, Wd1, bd1, Wd2, bd2, Wd3, bd3, out);
    }
}

// round 15
// speedup vs baseline: 1.1952x; 1.0090x over previous
#include <cuda_runtime.h>
#include <cuda_fp16.h>
#include <cstdint>

#define N_NODES  50000
#define N_EDGES  400000
#define N_GRAPHS 64

// ============================ device scratch ===============================
__device__ __half g_w1[256 * 512];         // [W1l|W1r]^T fp16  [256 n][512 k]
__device__ __half g_w2[64 * 128];          // [W2l|W2r]^T fp16  [64 n][128 k]
__device__ __half g_y1l[N_NODES * 128];    // x@W1l (fp16, for edge gather)
__device__ __half g_y1r[N_NODES * 128];    // x@W1r (fp16)
__device__ __half g_agg1[N_NODES * 128];   // fp16 edge-sum accumulator
__device__ float  g_cnt[N_NODES];
__device__ __half g_y2l[N_NODES * 32];     // h1@W2l (fp16)
__device__ __half g_y2r[N_NODES * 32];     // h1@W2r (fp16)
__device__ __half g_agg2[N_NODES * 32];    // fp16 edge-sum accumulator
__device__ float  g_gsum[N_GRAPHS * 32];
__device__ float  g_gcnt[N_GRAPHS];
__device__ int    g_ticket;

// ============== setup: zero accumulators + weight conversion ===============
__global__ void setup_kernel(const float* __restrict__ W1l, const float* __restrict__ W1r,
                             const float* __restrict__ W2l, const float* __restrict__ W2r) {
    size_t i = (size_t)blockIdx.x * blockDim.x + threadIdx.x;
    size_t stride = (size_t)gridDim.x * blockDim.x;
    if (i == 0) g_ticket = 0;
    for (size_t k = i; k < (size_t)N_NODES * 64; k += stride) ((uint32_t*)g_agg1)[k] = 0u;
    for (size_t k = i; k < (size_t)N_NODES * 16; k += stride) ((uint32_t*)g_agg2)[k] = 0u;
    for (size_t k = i; k < (size_t)N_NODES;      k += stride) g_cnt[k]  = 0.f;
    for (size_t k = i; k < (size_t)N_GRAPHS * 32; k += stride) g_gsum[k] = 0.f;
    for (size_t k = i; k < (size_t)N_GRAPHS;      k += stride) g_gcnt[k] = 0.f;
    for (size_t idx = i; idx < 256 * 512; idx += stride) {
        int n = (int)(idx >> 9), k = (int)(idx & 511);
        float v = (n < 128) ? W1l[k * 128 + n] : W1r[k * 128 + (n - 128)];
        g_w1[idx] = __float2half_rn(v);
    }
    for (size_t idx = i; idx < 64 * 128; idx += stride) {
        int n = (int)(idx >> 7), k = (int)(idx & 127);
        float v = (n < 32) ? W2l[k * 32 + n] : W2r[k * 32 + (n - 32)];
        g_w2[idx] = __float2half_rn(v);
    }
}

// ============================ helpers ======================================
__device__ __forceinline__ uint32_t su32(const void* p) {
    return (uint32_t)__cvta_generic_to_shared(p);
}
__device__ __forceinline__ uint32_t pack_h2(__half a, __half b) {
    __half2 t = __halves2half2(a, b);
    return *(uint32_t*)&t;
}
__device__ __forceinline__ uint2 cvt4h(float4 v) {
    return make_uint2(pack_h2(__float2half_rn(v.x), __float2half_rn(v.y)),
                      pack_h2(__float2half_rn(v.z), __float2half_rn(v.w)));
}
__device__ __forceinline__ void mma16816h(float* c, const uint32_t* a, const uint32_t* b) {
    asm volatile(
        "mma.sync.aligned.m16n8k16.row.col.f32.f16.f16.f32 "
        "{%0,%1,%2,%3}, {%4,%5,%6,%7}, {%8,%9}, {%0,%1,%2,%3};"
        : "+f"(c[0]), "+f"(c[1]), "+f"(c[2]), "+f"(c[3])
        : "r"(a[0]), "r"(a[1]), "r"(a[2]), "r"(a[3]), "r"(b[0]), "r"(b[1]));
}
__device__ __forceinline__ void ldsm4(uint32_t* r, uint32_t addr) {
    asm volatile("ldmatrix.sync.aligned.m8n8.x4.shared.b16 {%0,%1,%2,%3}, [%4];"
                 : "=r"(r[0]), "=r"(r[1]), "=r"(r[2]), "=r"(r[3]) : "r"(addr));
}
__device__ __forceinline__ void red_h8(__half* p, uint4 v) {
    asm volatile("red.global.add.noftz.v4.f16x2 [%0], {%1,%2,%3,%4};"
                 :: "l"(p), "r"(v.x), "r"(v.y), "r"(v.z), "r"(v.w) : "memory");
}

// ===== GEMM1: [y1l|y1r] = x[M,512] @ W1^T  (fp16, fused convert, BK=64) ====
// 512 threads, CTA tile 128(M) x 256(N), BK=64, 2-stage, mid-loop store.
#define G1_ROW 144
#define G1_STAGE 55296
#define SM_G1 (2 * G1_STAGE)

__global__ __launch_bounds__(512) void gemm1_mma(const float* __restrict__ x, int M) {
    extern __shared__ char smem[];
    const uint32_t sb = su32(smem);
    const int tid  = threadIdx.x;
    const int lane = tid & 31, wid = tid >> 5;
    const int wm = (wid & 3) * 32;
    const int wn = (wid >> 2) * 64;
    const int rowBase = blockIdx.x * 128;

    float acc[2][8][4];
#pragma unroll
    for (int i = 0; i < 2; i++)
#pragma unroll
        for (int j = 0; j < 8; j++)
#pragma unroll
            for (int q = 0; q < 4; q++) acc[i][j][q] = 0.f;

    const int g4 = lane & 3, gID = lane >> 2;
    const int sel = lane >> 3;
    const uint32_t rowInSel = (uint32_t)((sel & 1) * 8 + (lane & 7));
    const uint32_t colSel = (uint32_t)((sel >> 1) * 16);
    const uint32_t aOff = (wm + rowInSel) * G1_ROW + colSel;
    const uint32_t bOff = 18432 + (wn + rowInSel) * G1_ROW + colSel;

    const int arow = tid >> 2, aq = tid & 3;
    const int gra = rowBase + arow;
    const bool av = (gra < M);
    const size_t agi = (size_t)(av ? gra : 0) * 512 + aq * 16;
    const uint32_t sAo = arow * G1_ROW + aq * 32;
    const uint32_t bRow0 = tid >> 3, bQ = (uint32_t)(tid & 7);
    const size_t bgiBase = (size_t)bRow0 * 512 + bQ * 8;
    const uint32_t sBoBase = 18432 + bRow0 * G1_ROW + bQ * 16;

    float4 ra[4];
    uint4 rb[4];
    const float4 zf4 = make_float4(0.f, 0.f, 0.f, 0.f);

    auto loadRegs = [&](int kt) {
#pragma unroll
        for (int p = 0; p < 4; p++)
            ra[p] = av ? *(const float4*)(x + agi + kt + p * 4) : zf4;
#pragma unroll
        for (int p = 0; p < 4; p++)
            rb[p] = *(const uint4*)(g_w1 + bgiBase + (size_t)p * 64 * 512 + kt);
    };
    auto storeStage = [&](int s) {
        char* st = smem + s * G1_STAGE;
        uint2 h0 = cvt4h(ra[0]), h1 = cvt4h(ra[1]);
        *(uint4*)(st + sAo)      = make_uint4(h0.x, h0.y, h1.x, h1.y);
        h0 = cvt4h(ra[2]); h1 = cvt4h(ra[3]);
        *(uint4*)(st + sAo + 16) = make_uint4(h0.x, h0.y, h1.x, h1.y);
#pragma unroll
        for (int p = 0; p < 4; p++)
            *(uint4*)(st + sBoBase + p * (64 * G1_ROW)) = rb[p];
    };

    loadRegs(0);
    storeStage(0);
    __syncthreads();

    for (int it = 0; it < 8; it++) {
        const int s = it & 1;
        if (it < 7) loadRegs((it + 1) * 64);

        const uint32_t Ab = sb + s * G1_STAGE;
#pragma unroll
        for (int kk2 = 0; kk2 < 2; kk2++) {
            uint32_t a[2][4];
            ldsm4(a[0], Ab + aOff + kk2 * 32);
            ldsm4(a[1], Ab + aOff + 2304 + kk2 * 32);
#pragma unroll
            for (int ntp = 0; ntp < 4; ntp++) {
                uint32_t b[4];
                ldsm4(b, Ab + bOff + ntp * 2304 + kk2 * 32);
                uint32_t b0[2] = {b[0], b[2]};
                uint32_t b1[2] = {b[1], b[3]};
                mma16816h(acc[0][2 * ntp],     a[0], b0);
                mma16816h(acc[1][2 * ntp],     a[1], b0);
                mma16816h(acc[0][2 * ntp + 1], a[0], b1);
                mma16816h(acc[1][2 * ntp + 1], a[1], b1);
            }
        }
        if (it < 7) storeStage(s ^ 1);
#pragma unroll
        for (int kk2 = 2; kk2 < 4; kk2++) {
            uint32_t a[2][4];
            ldsm4(a[0], Ab + aOff + kk2 * 32);
            ldsm4(a[1], Ab + aOff + 2304 + kk2 * 32);
#pragma unroll
            for (int ntp = 0; ntp < 4; ntp++) {
                uint32_t b[4];
                ldsm4(b, Ab + bOff + ntp * 2304 + kk2 * 32);
                uint32_t b0[2] = {b[0], b[2]};
                uint32_t b1[2] = {b[1], b[3]};
                mma16816h(acc[0][2 * ntp],     a[0], b0);
                mma16816h(acc[1][2 * ntp],     a[1], b0);
                mma16816h(acc[0][2 * ntp + 1], a[0], b1);
                mma16816h(acc[1][2 * ntp + 1], a[1], b1);
            }
        }
        __syncthreads();
    }

    // epilogue: cols < 128 -> y1l fp16 ; cols >= 128 -> y1r fp16
#pragma unroll
    for (int mt = 0; mt < 2; mt++) {
        int r0 = rowBase + wm + mt * 16 + gID;
#pragma unroll
        for (int nt = 0; nt < 8; nt++) {
            int cc = wn + nt * 8 + g4 * 2;
            uint32_t p0 = pack_h2(__float2half_rn(acc[mt][nt][0]),
                                  __float2half_rn(acc[mt][nt][1]));
            uint32_t p1 = pack_h2(__float2half_rn(acc[mt][nt][2]),
                                  __float2half_rn(acc[mt][nt][3]));
            if (wn < 128) {
                if (r0 < M)     *(uint32_t*)(g_y1l + (size_t)r0 * 128 + cc) = p0;
                if (r0 + 8 < M) *(uint32_t*)(g_y1l + (size_t)(r0 + 8) * 128 + cc) = p1;
            } else {
                int cr = cc - 128;
                if (r0 < M)     *(uint32_t*)(g_y1r + (size_t)r0 * 128 + cr) = p0;
                if (r0 + 8 < M) *(uint32_t*)(g_y1r + (size_t)(r0 + 8) * 128 + cr) = p1;
            }
        }
    }
}

// ===== GEMM2 (fused SAGE epilogue, 2-stage register-prefetch pipeline) =====
__global__ __launch_bounds__(256) void gemm2_mma(const float* __restrict__ b1l, int M) {
    __shared__ __half sA[2][128][40], sB[2][64][40];

    const int tid  = threadIdx.x;
    const int lane = tid & 31, wid = tid >> 5;
    const int wm = (wid & 3) * 32;
    const int wn = (wid >> 2) * 32;
    const int rowBase = blockIdx.x * 128;

    float acc[2][4][4];
#pragma unroll
    for (int i = 0; i < 2; i++)
#pragma unroll
        for (int j = 0; j < 4; j++)
#pragma unroll
            for (int q = 0; q < 4; q++) acc[i][j][q] = 0.f;

    const int g4 = lane & 3, gID = lane >> 2;
    const int sel = lane >> 3;
    const uint32_t rowInSel = (uint32_t)((sel & 1) * 8 + (lane & 7));
    const uint32_t colSel = (uint32_t)((sel >> 1) * 16);
    const uint32_t aOff = (wm + rowInSel) * 80 + colSel;
    const uint32_t bOff = (wn + rowInSel) * 80 + colSel;
    const uint32_t aB0 = su32(sA), bB0 = su32(sB);

    const int arow0 = tid >> 2, aq = tid & 3;
    const int gr0 = rowBase + arow0, gr1 = gr0 + 64;
    const bool av0 = (gr0 < M), av1 = (gr1 < M);
    const float inv0 = av0 ? 1.0f / fmaxf(g_cnt[gr0], 1.0f) : 0.f;
    const float inv1 = av1 ? 1.0f / fmaxf(g_cnt[gr1], 1.0f) : 0.f;

    uint4  pagg[2];
    uint4  pr[2];
    float4 pbb[2];
    uint4  pwb;
    const int brow = tid >> 2, bq = tid & 3;

    auto loadRegs = [&](int kt) {
        const int kc = kt + aq * 8;
        pbb[0] = *(const float4*)(b1l + kc);
        pbb[1] = *(const float4*)(b1l + kc + 4);
#pragma unroll
        for (int p = 0; p < 2; p++) {
            const int gr = p ? gr1 : gr0;
            const bool av = p ? av1 : av0;
            if (av) {
                pagg[p] = *(const uint4*)(g_agg1 + (size_t)gr * 128 + kc);
                pr[p]   = *(const uint4*)(g_y1r + (size_t)gr * 128 + kc);
            } else {
                pagg[p] = make_uint4(0, 0, 0, 0);
                pr[p]   = make_uint4(0, 0, 0, 0);
            }
        }
        pwb = *(const uint4*)(g_w2 + (size_t)brow * 128 + kt + bq * 8);
    };
    auto storeStage = [&](int s) {
#pragma unroll
        for (int p = 0; p < 2; p++) {
            const bool av = p ? av1 : av0;
            const float inv = p ? inv1 : inv0;
            uint4 packed = make_uint4(0, 0, 0, 0);
            if (av) {
                const __half2* ah = (const __half2*)&pagg[p];
                const __half2* rh = (const __half2*)&pr[p];
                float2 a0 = __half22float2(ah[0]), a1 = __half22float2(ah[1]);
                float2 a2 = __half22float2(ah[2]), a3 = __half22float2(ah[3]);
                float2 r0 = __half22float2(rh[0]), r1 = __half22float2(rh[1]);
                float2 r2 = __half22float2(rh[2]), r3 = __half22float2(rh[3]);
                float4 o0, o1;
                o0.x = fmaxf(a0.x * inv + pbb[0].x + r0.x, 0.f);
                o0.y = fmaxf(a0.y * inv + pbb[0].y + r0.y, 0.f);
                o0.z = fmaxf(a1.x * inv + pbb[0].z + r1.x, 0.f);
                o0.w = fmaxf(a1.y * inv + pbb[0].w + r1.y, 0.f);
                o1.x = fmaxf(a2.x * inv + pbb[1].x + r2.x, 0.f);
                o1.y = fmaxf(a2.y * inv + pbb[1].y + r2.y, 0.f);
                o1.z = fmaxf(a3.x * inv + pbb[1].z + r3.x, 0.f);
                o1.w = fmaxf(a3.y * inv + pbb[1].w + r3.y, 0.f);
                uint2 h0 = cvt4h(o0), h1 = cvt4h(o1);
                packed = make_uint4(h0.x, h0.y, h1.x, h1.y);
            }
            *(uint4*)&sA[s][arow0 + p * 64][aq * 8] = packed;
        }
        *(uint4*)&sB[s][brow][bq * 8] = pwb;
    };

    loadRegs(0);
    storeStage(0);
    __syncthreads();

    for (int it = 0; it < 4; it++) {
        const int s = it & 1;
        if (it < 3) loadRegs((it + 1) * 32);

        const uint32_t aB = aB0 + (uint32_t)s * 10240;
        const uint32_t bB = bB0 + (uint32_t)s * 5120;
#pragma unroll
        for (int kk2 = 0; kk2 < 2; kk2++) {
            uint32_t a[2][4];
            ldsm4(a[0], aB + aOff + kk2 * 32);
            ldsm4(a[1], aB + aOff + 1280 + kk2 * 32);
#pragma unroll
            for (int ntp = 0; ntp < 2; ntp++) {
                uint32_t b[4];
                ldsm4(b, bB + bOff + ntp * 1280 + kk2 * 32);
                uint32_t b0[2] = {b[0], b[2]};
                uint32_t b1[2] = {b[1], b[3]};
                mma16816h(acc[0][2 * ntp],     a[0], b0);
                mma16816h(acc[1][2 * ntp],     a[1], b0);
                mma16816h(acc[0][2 * ntp + 1], a[0], b1);
                mma16816h(acc[1][2 * ntp + 1], a[1], b1);
            }
        }
        if (it < 3) storeStage(s ^ 1);
        __syncthreads();
    }

    // epilogue: cols < 32 -> y2l fp16 ; cols >= 32 -> y2r fp16
#pragma unroll
    for (int mt = 0; mt < 2; mt++) {
        int r0 = rowBase + wm + mt * 16 + gID;
#pragma unroll
        for (int nt = 0; nt < 4; nt++) {
            int cc = wn + nt * 8 + g4 * 2;
            uint32_t p0 = pack_h2(__float2half_rn(acc[mt][nt][0]),
                                  __float2half_rn(acc[mt][nt][1]));
            uint32_t p1 = pack_h2(__float2half_rn(acc[mt][nt][2]),
                                  __float2half_rn(acc[mt][nt][3]));
            if (cc < 32) {
                if (r0 < M)     *(uint32_t*)(g_y2l + (size_t)r0 * 32 + cc) = p0;
                if (r0 + 8 < M) *(uint32_t*)(g_y2l + (size_t)(r0 + 8) * 32 + cc) = p1;
            } else {
                int cr = cc - 32;
                if (r0 < M)     *(uint32_t*)(g_y2r + (size_t)r0 * 32 + cr) = p0;
                if (r0 + 8 < M) *(uint32_t*)(g_y2r + (size_t)(r0 + 8) * 32 + cr) = p1;
            }
        }
    }
}

// -------- edge aggregation, layer 1 (128 fp16 feats, 16 threads/edge) ------
__global__ void edge_agg1(const int* __restrict__ ei) {
    int gtid = blockIdx.x * blockDim.x + threadIdx.x;
    int e = gtid >> 4;
    int lane = gtid & 15;
    if (e >= N_EDGES) return;
    int src = ei[e];
    int dst = ei[N_EDGES + e];
    uint4 v = *(const uint4*)(g_y1l + (size_t)src * 128 + lane * 8);
    red_h8(g_agg1 + (size_t)dst * 128 + lane * 8, v);
    if (lane == 0) atomicAdd(&g_cnt[dst], 1.0f);
}

// -------- edge aggregation, layer 2 (32 fp16 feats, 4 threads/edge) --------
__global__ void edge_agg2(const int* __restrict__ ei) {
    int gtid = blockIdx.x * blockDim.x + threadIdx.x;
    int e = gtid >> 2;
    int lane = gtid & 3;
    if (e >= N_EDGES) return;
    int src = ei[e];
    int dst = ei[N_EDGES + e];
    uint4 v = *(const uint4*)(g_y2l + (size_t)src * 32 + lane * 8);
    red_h8(g_agg2 + (size_t)dst * 32 + lane * 8, v);
}

// ====== fused layer-2 epilogue + per-graph mean pool + final MLP ===========
__global__ void pool_kernel(const int* __restrict__ batch, const float* __restrict__ b2l,
                            const float* __restrict__ Wl1, const float* __restrict__ bl1,
                            const float* __restrict__ Wl2, const float* __restrict__ bl2,
                            const float* __restrict__ Wd1, const float* __restrict__ bd1,
                            const float* __restrict__ Wd2, const float* __restrict__ bd2,
                            const float* __restrict__ Wd3, const float* __restrict__ bd3,
                            float* __restrict__ out) {
    __shared__ bool sLast;
    __shared__ float sWl1[1024], sWl2[512], sWd1[512], sWd2[1024], sWd3[1600];
    __shared__ float sbl1[32], sbl2[16], sbd1[32], sbd2[32], sbd3[50];

    int f = threadIdx.x;           // 32
    int yid = threadIdx.y;         // 8
    int tid = yid * 32 + f;        // 0..255
    int n0 = blockIdx.x * 128 + yid;
    float b = b2l[f];
    float acc = 0.f, cacc = 0.f;
    int cur = -1;
    for (int it = 0; it < 16; it++) {
        int n = n0 + it * 8;
        if (n < N_NODES) {
            int g = batch[n];
            if (g != cur) {
                if (cur >= 0) {
                    atomicAdd(&g_gsum[cur * 32 + f], acc);
                    if (f == 0) atomicAdd(&g_gcnt[cur], cacc);
                }
                cur = g; acc = 0.f; cacc = 0.f;
            }
            float inv = 1.0f / fmaxf(g_cnt[n], 1.0f);
            float v = __half2float(g_agg2[(size_t)n * 32 + f]) * inv + b +
                      __half2float(g_y2r[(size_t)n * 32 + f]);
            acc += fmaxf(v, 0.f);
            cacc += 1.f;
        }
    }
    if (cur >= 0) {
        atomicAdd(&g_gsum[cur * 32 + f], acc);
        if (f == 0) atomicAdd(&g_gcnt[cur], cacc);
    }

    __threadfence();
    __syncthreads();
    if (tid == 0) {
        int v = atomicAdd(&g_ticket, 1);
        sLast = (v == (int)gridDim.x - 1);
    }
    __syncthreads();
    if (!sLast) return;

    for (int i = tid; i < 1024; i += 256) sWl1[i] = Wl1[i];
    for (int i = tid; i < 512;  i += 256) sWl2[i] = Wl2[i];
    for (int i = tid; i < 512;  i += 256) sWd1[i] = Wd1[i];
    for (int i = tid; i < 1024; i += 256) sWd2[i] = Wd2[i];
    for (int i = tid; i < 1600; i += 256) sWd3[i] = Wd3[i];
    if (tid < 32) sbl1[tid] = bl1[tid];
    if (tid < 16) sbl2[tid] = bl2[tid];
    if (tid < 32) sbd1[tid] = bd1[tid];
    if (tid < 32) sbd2[tid] = bd2[tid];
    if (tid < 50) sbd3[tid] = bd3[tid];
    __syncthreads();
    if (tid >= N_GRAPHS) return;
    int t = tid;

    float gv[32];
    float inv = 1.0f / fmaxf(g_gcnt[t], 1.0f);
#pragma unroll
    for (int i = 0; i < 32; i++) gv[i] = g_gsum[t * 32 + i] * inv;

    float a[32];
#pragma unroll
    for (int j = 0; j < 32; j++) {
        float s = sbl1[j];
#pragma unroll
        for (int i = 0; i < 32; i++) s = fmaf(gv[i], sWl1[i * 32 + j], s);
        a[j] = fmaxf(s, 0.f);
    }
    float enc[16];
#pragma unroll
    for (int j = 0; j < 16; j++) {
        float s = sbl2[j];
#pragma unroll
        for (int i = 0; i < 32; i++) s = fmaf(a[i], sWl2[i * 16 + j], s);
        enc[j] = s > 0.f ? s : 0.1f * s;
    }
#pragma unroll
    for (int j = 0; j < 16; j++) out[t * 16 + j] = enc[j];

    float z1[32];
#pragma unroll
    for (int j = 0; j < 32; j++) {
        float s = sbd1[j];
#pragma unroll
        for (int i = 0; i < 16; i++) s = fmaf(enc[i], sWd1[i * 32 + j], s);
        z1[j] = s > 0.f ? s : 0.1f * s;
    }
    float z2[32];
#pragma unroll
    for (int j = 0; j < 32; j++) {
        float s = sbd2[j];
#pragma unroll
        for (int i = 0; i < 32; i++) s = fmaf(z1[i], sWd2[i * 32 + j], s);
        z2[j] = s > 0.f ? s : 0.1f * s;
    }
#pragma unroll
    for (int j = 0; j < 50; j++) {
        float s = sbd3[j];
#pragma unroll
        for (int i = 0; i < 32; i++) s = fmaf(z2[i], sWd3[i * 50 + j], s);
        out[1024 + t * 50 + j] = s;
    }
}

// ---------------- launch ----------------------------------------------------
extern "C" void kernel_launch(void* const* d_in, const int* in_sizes, int n_in,
                              void* d_out, int out_size) {
    const float* x   = (const float*)d_in[0];
    const int*   ei  = (const int*)d_in[1];
    const int*   bat = (const int*)d_in[2];
    const float* W1l = (const float*)d_in[3];
    const float* b1l = (const float*)d_in[4];
    const float* W1r = (const float*)d_in[5];
    const float* W2l = (const float*)d_in[6];
    const float* b2l = (const float*)d_in[7];
    const float* W2r = (const float*)d_in[8];
    const float* Wl1 = (const float*)d_in[9];
    const float* bl1 = (const float*)d_in[10];
    const float* Wl2 = (const float*)d_in[11];
    const float* bl2 = (const float*)d_in[12];
    const float* Wd1 = (const float*)d_in[13];
    const float* bd1 = (const float*)d_in[14];
    const float* Wd2 = (const float*)d_in[15];
    const float* bd2 = (const float*)d_in[16];
    const float* Wd3 = (const float*)d_in[17];
    const float* bd3 = (const float*)d_in[18];
    float* out = (float*)d_out;

    static bool attr_set = false;
    if (!attr_set) {
        cudaFuncSetAttribute(gemm1_mma, cudaFuncAttributeMaxDynamicSharedMemorySize, SM_G1);
        attr_set = true;
    }

    setup_kernel<<<592, 256>>>(W1l, W1r, W2l, W2r);

    // GEMM1 (tensor pipe, fp16, fused convert, BK=64, mid-loop store)
    gemm1_mma<<<(N_NODES + 127) / 128, 512, SM_G1>>>(x, N_NODES);

    edge_agg1<<<25000, 256>>>(ei);   // fp16 v4 reductions, 16 thr/edge

    // GEMM2 (tensor pipe, fused SAGE epilogue, 2-stage prefetch)
    gemm2_mma<<<(N_NODES + 127) / 128, 256>>>(b1l, N_NODES);

    edge_agg2<<<6250, 256>>>(ei);    // fp16 v4 reductions, 4 thr/edge

    // pool + fused MLP (last-block ticket)
    {
        dim3 blk(32, 8);
        pool_kernel<<<(N_NODES + 127) / 128, blk>>>(bat, b2l,
            Wl1, bl1, Wl2, bl2, Wd1, bd1, Wd2, bd2, Wd3, bd3, out);
    }
}

// round 16
// speedup vs baseline: 1.2036x; 1.0070x over previous
#include <cuda_runtime.h>
#include <cuda_fp16.h>
#include <cstdint>

#define N_NODES  50000
#define N_EDGES  400000
#define N_GRAPHS 64

// ============================ device scratch ===============================
__device__ __half g_w1[256 * 512];         // [W1l|W1r]^T fp16  [256 n][512 k]
__device__ __half g_w2[64 * 128];          // [W2l|W2r]^T fp16  [64 n][128 k]
__device__ __half g_y1l[N_NODES * 128];    // x@W1l (fp16, for edge gather)
__device__ __half g_y1r[N_NODES * 128];    // x@W1r (fp16)
__device__ __half g_agg1[N_NODES * 128];   // fp16 edge-sum accumulator
__device__ float  g_cnt[N_NODES];
__device__ __half g_y2l[N_NODES * 32];     // h1@W2l (fp16)
__device__ __half g_y2r[N_NODES * 32];     // h1@W2r (fp16)
__device__ __half g_agg2[N_NODES * 32];    // fp16 edge-sum accumulator
__device__ float  g_gsum[N_GRAPHS * 32];
__device__ float  g_gcnt[N_GRAPHS];
__device__ int    g_ticket;

// ============== setup: zero accumulators + weight conversion ===============
__global__ void setup_kernel(const float* __restrict__ W1l, const float* __restrict__ W1r,
                             const float* __restrict__ W2l, const float* __restrict__ W2r) {
    size_t i = (size_t)blockIdx.x * blockDim.x + threadIdx.x;
    size_t stride = (size_t)gridDim.x * blockDim.x;
    if (i == 0) g_ticket = 0;
    for (size_t k = i; k < (size_t)N_NODES * 64; k += stride) ((uint32_t*)g_agg1)[k] = 0u;
    for (size_t k = i; k < (size_t)N_NODES * 16; k += stride) ((uint32_t*)g_agg2)[k] = 0u;
    for (size_t k = i; k < (size_t)N_NODES;      k += stride) g_cnt[k]  = 0.f;
    for (size_t k = i; k < (size_t)N_GRAPHS * 32; k += stride) g_gsum[k] = 0.f;
    for (size_t k = i; k < (size_t)N_GRAPHS;      k += stride) g_gcnt[k] = 0.f;
    for (size_t idx = i; idx < 256 * 512; idx += stride) {
        int n = (int)(idx >> 9), k = (int)(idx & 511);
        float v = (n < 128) ? W1l[k * 128 + n] : W1r[k * 128 + (n - 128)];
        g_w1[idx] = __float2half_rn(v);
    }
    for (size_t idx = i; idx < 64 * 128; idx += stride) {
        int n = (int)(idx >> 7), k = (int)(idx & 127);
        float v = (n < 32) ? W2l[k * 32 + n] : W2r[k * 32 + (n - 32)];
        g_w2[idx] = __float2half_rn(v);
    }
}

// ============================ helpers ======================================
__device__ __forceinline__ uint32_t su32(const void* p) {
    return (uint32_t)__cvta_generic_to_shared(p);
}
__device__ __forceinline__ uint32_t pack_h2(__half a, __half b) {
    __half2 t = __halves2half2(a, b);
    return *(uint32_t*)&t;
}
__device__ __forceinline__ uint2 cvt4h(float4 v) {
    return make_uint2(pack_h2(__float2half_rn(v.x), __float2half_rn(v.y)),
                      pack_h2(__float2half_rn(v.z), __float2half_rn(v.w)));
}
__device__ __forceinline__ void mma16816h(float* c, const uint32_t* a, const uint32_t* b) {
    asm volatile(
        "mma.sync.aligned.m16n8k16.row.col.f32.f16.f16.f32 "
        "{%0,%1,%2,%3}, {%4,%5,%6,%7}, {%8,%9}, {%0,%1,%2,%3};"
        : "+f"(c[0]), "+f"(c[1]), "+f"(c[2]), "+f"(c[3])
        : "r"(a[0]), "r"(a[1]), "r"(a[2]), "r"(a[3]), "r"(b[0]), "r"(b[1]));
}
__device__ __forceinline__ void ldsm4(uint32_t* r, uint32_t addr) {
    asm volatile("ldmatrix.sync.aligned.m8n8.x4.shared.b16 {%0,%1,%2,%3}, [%4];"
                 : "=r"(r[0]), "=r"(r[1]), "=r"(r[2]), "=r"(r[3]) : "r"(addr));
}
__device__ __forceinline__ void red_h8(__half* p, uint4 v) {
    asm volatile("red.global.add.noftz.v4.f16x2 [%0], {%1,%2,%3,%4};"
                 :: "l"(p), "r"(v.x), "r"(v.y), "r"(v.z), "r"(v.w) : "memory");
}

// ===== GEMM1: [y1l|y1r] = x[M,512] @ W1^T  (fp16, fused convert, BK=64) ====
// 512 threads, CTA tile 128(M) x 256(N), BK=64, 2-stage, mid-loop store,
// B-fragment software pipeline in the inner loop.
#define G1_ROW 144
#define G1_STAGE 55296
#define SM_G1 (2 * G1_STAGE)

__global__ __launch_bounds__(512) void gemm1_mma(const float* __restrict__ x, int M) {
    extern __shared__ char smem[];
    const uint32_t sb = su32(smem);
    const int tid  = threadIdx.x;
    const int lane = tid & 31, wid = tid >> 5;
    const int wm = (wid & 3) * 32;
    const int wn = (wid >> 2) * 64;
    const int rowBase = blockIdx.x * 128;

    float acc[2][8][4];
#pragma unroll
    for (int i = 0; i < 2; i++)
#pragma unroll
        for (int j = 0; j < 8; j++)
#pragma unroll
            for (int q = 0; q < 4; q++) acc[i][j][q] = 0.f;

    const int g4 = lane & 3, gID = lane >> 2;
    const int sel = lane >> 3;
    const uint32_t rowInSel = (uint32_t)((sel & 1) * 8 + (lane & 7));
    const uint32_t colSel = (uint32_t)((sel >> 1) * 16);
    const uint32_t aOff = (wm + rowInSel) * G1_ROW + colSel;
    const uint32_t bOff = 18432 + (wn + rowInSel) * G1_ROW + colSel;

    const int arow = tid >> 2, aq = tid & 3;
    const int gra = rowBase + arow;
    const bool av = (gra < M);
    const size_t agi = (size_t)(av ? gra : 0) * 512 + aq * 16;
    const uint32_t sAo = arow * G1_ROW + aq * 32;
    const uint32_t bRow0 = tid >> 3, bQ = (uint32_t)(tid & 7);
    const size_t bgiBase = (size_t)bRow0 * 512 + bQ * 8;
    const uint32_t sBoBase = 18432 + bRow0 * G1_ROW + bQ * 16;

    float4 ra[4];
    uint4 rb[4];
    const float4 zf4 = make_float4(0.f, 0.f, 0.f, 0.f);

    auto loadRegs = [&](int kt) {
#pragma unroll
        for (int p = 0; p < 4; p++)
            ra[p] = av ? *(const float4*)(x + agi + kt + p * 4) : zf4;
#pragma unroll
        for (int p = 0; p < 4; p++)
            rb[p] = *(const uint4*)(g_w1 + bgiBase + (size_t)p * 64 * 512 + kt);
    };
    auto storeStage = [&](int s) {
        char* st = smem + s * G1_STAGE;
        uint2 h0 = cvt4h(ra[0]), h1 = cvt4h(ra[1]);
        *(uint4*)(st + sAo)      = make_uint4(h0.x, h0.y, h1.x, h1.y);
        h0 = cvt4h(ra[2]); h1 = cvt4h(ra[3]);
        *(uint4*)(st + sAo + 16) = make_uint4(h0.x, h0.y, h1.x, h1.y);
#pragma unroll
        for (int p = 0; p < 4; p++)
            *(uint4*)(st + sBoBase + p * (64 * G1_ROW)) = rb[p];
    };

    // one kk2 step with B-fragment double buffering
    auto mmaStep = [&](uint32_t Ab, int kk2) {
        uint32_t a[2][4];
        ldsm4(a[0], Ab + aOff + kk2 * 32);
        ldsm4(a[1], Ab + aOff + 2304 + kk2 * 32);
        uint32_t bc[4];
        ldsm4(bc, Ab + bOff + kk2 * 32);
#pragma unroll
        for (int ntp = 0; ntp < 4; ntp++) {
            uint32_t bn[4];
            if (ntp < 3) ldsm4(bn, Ab + bOff + (ntp + 1) * 2304 + kk2 * 32);
            uint32_t b0[2] = {bc[0], bc[2]};
            uint32_t b1[2] = {bc[1], bc[3]};
            mma16816h(acc[0][2 * ntp],     a[0], b0);
            mma16816h(acc[1][2 * ntp],     a[1], b0);
            mma16816h(acc[0][2 * ntp + 1], a[0], b1);
            mma16816h(acc[1][2 * ntp + 1], a[1], b1);
            if (ntp < 3) { bc[0] = bn[0]; bc[1] = bn[1]; bc[2] = bn[2]; bc[3] = bn[3]; }
        }
    };

    loadRegs(0);
    storeStage(0);
    __syncthreads();

    for (int it = 0; it < 8; it++) {
        const int s = it & 1;
        if (it < 7) loadRegs((it + 1) * 64);

        const uint32_t Ab = sb + s * G1_STAGE;
        mmaStep(Ab, 0);
        mmaStep(Ab, 1);
        if (it < 7) storeStage(s ^ 1);
        mmaStep(Ab, 2);
        mmaStep(Ab, 3);
        __syncthreads();
    }

    // epilogue: cols < 128 -> y1l fp16 ; cols >= 128 -> y1r fp16
#pragma unroll
    for (int mt = 0; mt < 2; mt++) {
        int r0 = rowBase + wm + mt * 16 + gID;
#pragma unroll
        for (int nt = 0; nt < 8; nt++) {
            int cc = wn + nt * 8 + g4 * 2;
            uint32_t p0 = pack_h2(__float2half_rn(acc[mt][nt][0]),
                                  __float2half_rn(acc[mt][nt][1]));
            uint32_t p1 = pack_h2(__float2half_rn(acc[mt][nt][2]),
                                  __float2half_rn(acc[mt][nt][3]));
            if (wn < 128) {
                if (r0 < M)     *(uint32_t*)(g_y1l + (size_t)r0 * 128 + cc) = p0;
                if (r0 + 8 < M) *(uint32_t*)(g_y1l + (size_t)(r0 + 8) * 128 + cc) = p1;
            } else {
                int cr = cc - 128;
                if (r0 < M)     *(uint32_t*)(g_y1r + (size_t)r0 * 128 + cr) = p0;
                if (r0 + 8 < M) *(uint32_t*)(g_y1r + (size_t)(r0 + 8) * 128 + cr) = p1;
            }
        }
    }
}

// ===== GEMM2 (fused SAGE epilogue, 2-stage register-prefetch pipeline) =====
__global__ __launch_bounds__(256, 3) void gemm2_mma(const float* __restrict__ b1l, int M) {
    __shared__ __half sA[2][128][40], sB[2][64][40];

    const int tid  = threadIdx.x;
    const int lane = tid & 31, wid = tid >> 5;
    const int wm = (wid & 3) * 32;
    const int wn = (wid >> 2) * 32;
    const int rowBase = blockIdx.x * 128;

    float acc[2][4][4];
#pragma unroll
    for (int i = 0; i < 2; i++)
#pragma unroll
        for (int j = 0; j < 4; j++)
#pragma unroll
            for (int q = 0; q < 4; q++) acc[i][j][q] = 0.f;

    const int g4 = lane & 3, gID = lane >> 2;
    const int sel = lane >> 3;
    const uint32_t rowInSel = (uint32_t)((sel & 1) * 8 + (lane & 7));
    const uint32_t colSel = (uint32_t)((sel >> 1) * 16);
    const uint32_t aOff = (wm + rowInSel) * 80 + colSel;
    const uint32_t bOff = (wn + rowInSel) * 80 + colSel;
    const uint32_t aB0 = su32(sA), bB0 = su32(sB);

    const int arow0 = tid >> 2, aq = tid & 3;
    const int gr0 = rowBase + arow0, gr1 = gr0 + 64;
    const bool av0 = (gr0 < M), av1 = (gr1 < M);
    const float inv0 = av0 ? 1.0f / fmaxf(g_cnt[gr0], 1.0f) : 0.f;
    const float inv1 = av1 ? 1.0f / fmaxf(g_cnt[gr1], 1.0f) : 0.f;

    uint4  pagg[2];
    uint4  pr[2];
    float4 pbb[2];
    uint4  pwb;
    const int brow = tid >> 2, bq = tid & 3;

    auto loadRegs = [&](int kt) {
        const int kc = kt + aq * 8;
        pbb[0] = *(const float4*)(b1l + kc);
        pbb[1] = *(const float4*)(b1l + kc + 4);
#pragma unroll
        for (int p = 0; p < 2; p++) {
            const int gr = p ? gr1 : gr0;
            const bool av = p ? av1 : av0;
            if (av) {
                pagg[p] = *(const uint4*)(g_agg1 + (size_t)gr * 128 + kc);
                pr[p]   = *(const uint4*)(g_y1r + (size_t)gr * 128 + kc);
            } else {
                pagg[p] = make_uint4(0, 0, 0, 0);
                pr[p]   = make_uint4(0, 0, 0, 0);
            }
        }
        pwb = *(const uint4*)(g_w2 + (size_t)brow * 128 + kt + bq * 8);
    };
    auto storeStage = [&](int s) {
#pragma unroll
        for (int p = 0; p < 2; p++) {
            const bool av = p ? av1 : av0;
            const float inv = p ? inv1 : inv0;
            uint4 packed = make_uint4(0, 0, 0, 0);
            if (av) {
                const __half2* ah = (const __half2*)&pagg[p];
                const __half2* rh = (const __half2*)&pr[p];
                float2 a0 = __half22float2(ah[0]), a1 = __half22float2(ah[1]);
                float2 a2 = __half22float2(ah[2]), a3 = __half22float2(ah[3]);
                float2 r0 = __half22float2(rh[0]), r1 = __half22float2(rh[1]);
                float2 r2 = __half22float2(rh[2]), r3 = __half22float2(rh[3]);
                float4 o0, o1;
                o0.x = fmaxf(a0.x * inv + pbb[0].x + r0.x, 0.f);
                o0.y = fmaxf(a0.y * inv + pbb[0].y + r0.y, 0.f);
                o0.z = fmaxf(a1.x * inv + pbb[0].z + r1.x, 0.f);
                o0.w = fmaxf(a1.y * inv + pbb[0].w + r1.y, 0.f);
                o1.x = fmaxf(a2.x * inv + pbb[1].x + r2.x, 0.f);
                o1.y = fmaxf(a2.y * inv + pbb[1].y + r2.y, 0.f);
                o1.z = fmaxf(a3.x * inv + pbb[1].z + r3.x, 0.f);
                o1.w = fmaxf(a3.y * inv + pbb[1].w + r3.y, 0.f);
                uint2 h0 = cvt4h(o0), h1 = cvt4h(o1);
                packed = make_uint4(h0.x, h0.y, h1.x, h1.y);
            }
            *(uint4*)&sA[s][arow0 + p * 64][aq * 8] = packed;
        }
        *(uint4*)&sB[s][brow][bq * 8] = pwb;
    };

    loadRegs(0);
    storeStage(0);
    __syncthreads();

    for (int it = 0; it < 4; it++) {
        const int s = it & 1;
        if (it < 3) loadRegs((it + 1) * 32);

        const uint32_t aB = aB0 + (uint32_t)s * 10240;
        const uint32_t bB = bB0 + (uint32_t)s * 5120;
#pragma unroll
        for (int kk2 = 0; kk2 < 2; kk2++) {
            uint32_t a[2][4];
            ldsm4(a[0], aB + aOff + kk2 * 32);
            ldsm4(a[1], aB + aOff + 1280 + kk2 * 32);
#pragma unroll
            for (int ntp = 0; ntp < 2; ntp++) {
                uint32_t b[4];
                ldsm4(b, bB + bOff + ntp * 1280 + kk2 * 32);
                uint32_t b0[2] = {b[0], b[2]};
                uint32_t b1[2] = {b[1], b[3]};
                mma16816h(acc[0][2 * ntp],     a[0], b0);
                mma16816h(acc[1][2 * ntp],     a[1], b0);
                mma16816h(acc[0][2 * ntp + 1], a[0], b1);
                mma16816h(acc[1][2 * ntp + 1], a[1], b1);
            }
        }
        if (it < 3) storeStage(s ^ 1);
        __syncthreads();
    }

    // epilogue: cols < 32 -> y2l fp16 ; cols >= 32 -> y2r fp16
#pragma unroll
    for (int mt = 0; mt < 2; mt++) {
        int r0 = rowBase + wm + mt * 16 + gID;
#pragma unroll
        for (int nt = 0; nt < 4; nt++) {
            int cc = wn + nt * 8 + g4 * 2;
            uint32_t p0 = pack_h2(__float2half_rn(acc[mt][nt][0]),
                                  __float2half_rn(acc[mt][nt][1]));
            uint32_t p1 = pack_h2(__float2half_rn(acc[mt][nt][2]),
                                  __float2half_rn(acc[mt][nt][3]));
            if (cc < 32) {
                if (r0 < M)     *(uint32_t*)(g_y2l + (size_t)r0 * 32 + cc) = p0;
                if (r0 + 8 < M) *(uint32_t*)(g_y2l + (size_t)(r0 + 8) * 32 + cc) = p1;
            } else {
                int cr = cc - 32;
                if (r0 < M)     *(uint32_t*)(g_y2r + (size_t)r0 * 32 + cr) = p0;
                if (r0 + 8 < M) *(uint32_t*)(g_y2r + (size_t)(r0 + 8) * 32 + cr) = p1;
            }
        }
    }
}

// -------- edge aggregation, layer 1 (128 fp16 feats, 16 threads/edge) ------
__global__ void edge_agg1(const int* __restrict__ ei) {
    int gtid = blockIdx.x * blockDim.x + threadIdx.x;
    int e = gtid >> 4;
    int lane = gtid & 15;
    if (e >= N_EDGES) return;
    int src = ei[e];
    int dst = ei[N_EDGES + e];
    uint4 v = *(const uint4*)(g_y1l + (size_t)src * 128 + lane * 8);
    red_h8(g_agg1 + (size_t)dst * 128 + lane * 8, v);
    if (lane == 0) atomicAdd(&g_cnt[dst], 1.0f);
}

// -------- edge aggregation, layer 2 (32 fp16 feats, 4 threads/edge) --------
__global__ void edge_agg2(const int* __restrict__ ei) {
    int gtid = blockIdx.x * blockDim.x + threadIdx.x;
    int e = gtid >> 2;
    int lane = gtid & 3;
    if (e >= N_EDGES) return;
    int src = ei[e];
    int dst = ei[N_EDGES + e];
    uint4 v = *(const uint4*)(g_y2l + (size_t)src * 32 + lane * 8);
    red_h8(g_agg2 + (size_t)dst * 32 + lane * 8, v);
}

// ====== fused layer-2 epilogue + per-graph mean pool + final MLP ===========
__global__ void pool_kernel(const int* __restrict__ batch, const float* __restrict__ b2l,
                            const float* __restrict__ Wl1, const float* __restrict__ bl1,
                            const float* __restrict__ Wl2, const float* __restrict__ bl2,
                            const float* __restrict__ Wd1, const float* __restrict__ bd1,
                            const float* __restrict__ Wd2, const float* __restrict__ bd2,
                            const float* __restrict__ Wd3, const float* __restrict__ bd3,
                            float* __restrict__ out) {
    __shared__ bool sLast;
    __shared__ float sWl1[1024], sWl2[512], sWd1[512], sWd2[1024], sWd3[1600];
    __shared__ float sbl1[32], sbl2[16], sbd1[32], sbd2[32], sbd3[50];

    int f = threadIdx.x;           // 32
    int yid = threadIdx.y;         // 8
    int tid = yid * 32 + f;        // 0..255
    int n0 = blockIdx.x * 128 + yid;
    float b = b2l[f];
    float acc = 0.f, cacc = 0.f;
    int cur = -1;
    for (int it = 0; it < 16; it++) {
        int n = n0 + it * 8;
        if (n < N_NODES) {
            int g = batch[n];
            if (g != cur) {
                if (cur >= 0) {
                    atomicAdd(&g_gsum[cur * 32 + f], acc);
                    if (f == 0) atomicAdd(&g_gcnt[cur], cacc);
                }
                cur = g; acc = 0.f; cacc = 0.f;
            }
            float inv = 1.0f / fmaxf(g_cnt[n], 1.0f);
            float v = __half2float(g_agg2[(size_t)n * 32 + f]) * inv + b +
                      __half2float(g_y2r[(size_t)n * 32 + f]);
            acc += fmaxf(v, 0.f);
            cacc += 1.f;
        }
    }
    if (cur >= 0) {
        atomicAdd(&g_gsum[cur * 32 + f], acc);
        if (f == 0) atomicAdd(&g_gcnt[cur], cacc);
    }

    __threadfence();
    __syncthreads();
    if (tid == 0) {
        int v = atomicAdd(&g_ticket, 1);
        sLast = (v == (int)gridDim.x - 1);
    }
    __syncthreads();
    if (!sLast) return;

    for (int i = tid; i < 1024; i += 256) sWl1[i] = Wl1[i];
    for (int i = tid; i < 512;  i += 256) sWl2[i] = Wl2[i];
    for (int i = tid; i < 512;  i += 256) sWd1[i] = Wd1[i];
    for (int i = tid; i < 1024; i += 256) sWd2[i] = Wd2[i];
    for (int i = tid; i < 1600; i += 256) sWd3[i] = Wd3[i];
    if (tid < 32) sbl1[tid] = bl1[tid];
    if (tid < 16) sbl2[tid] = bl2[tid];
    if (tid < 32) sbd1[tid] = bd1[tid];
    if (tid < 32) sbd2[tid] = bd2[tid];
    if (tid < 50) sbd3[tid] = bd3[tid];
    __syncthreads();
    if (tid >= N_GRAPHS) return;
    int t = tid;

    float gv[32];
    float inv = 1.0f / fmaxf(g_gcnt[t], 1.0f);
#pragma unroll
    for (int i = 0; i < 32; i++) gv[i] = g_gsum[t * 32 + i] * inv;

    float a[32];
#pragma unroll
    for (int j = 0; j < 32; j++) {
        float s = sbl1[j];
#pragma unroll
        for (int i = 0; i < 32; i++) s = fmaf(gv[i], sWl1[i * 32 + j], s);
        a[j] = fmaxf(s, 0.f);
    }
    float enc[16];
#pragma unroll
    for (int j = 0; j < 16; j++) {
        float s = sbl2[j];
#pragma unroll
        for (int i = 0; i < 32; i++) s = fmaf(a[i], sWl2[i * 16 + j], s);
        enc[j] = s > 0.f ? s : 0.1f * s;
    }
#pragma unroll
    for (int j = 0; j < 16; j++) out[t * 16 + j] = enc[j];

    float z1[32];
#pragma unroll
    for (int j = 0; j < 32; j++) {
        float s = sbd1[j];
#pragma unroll
        for (int i = 0; i < 16; i++) s = fmaf(enc[i], sWd1[i * 32 + j], s);
        z1[j] = s > 0.f ? s : 0.1f * s;
    }
    float z2[32];
#pragma unroll
    for (int j = 0; j < 32; j++) {
        float s = sbd2[j];
#pragma unroll
        for (int i = 0; i < 32; i++) s = fmaf(z1[i], sWd2[i * 32 + j], s);
        z2[j] = s > 0.f ? s : 0.1f * s;
    }
#pragma unroll
    for (int j = 0; j < 50; j++) {
        float s = sbd3[j];
#pragma unroll
        for (int i = 0; i < 32; i++) s = fmaf(z2[i], sWd3[i * 50 + j], s);
        out[1024 + t * 50 + j] = s;
    }
}

// ---------------- launch ----------------------------------------------------
extern "C" void kernel_launch(void* const* d_in, const int* in_sizes, int n_in,
                              void* d_out, int out_size) {
    const float* x   = (const float*)d_in[0];
    const int*   ei  = (const int*)d_in[1];
    const int*   bat = (const int*)d_in[2];
    const float* W1l = (const float*)d_in[3];
    const float* b1l = (const float*)d_in[4];
    const float* W1r = (const float*)d_in[5];
    const float* W2l = (const float*)d_in[6];
    const float* b2l = (const float*)d_in[7];
    const float* W2r = (const float*)d_in[8];
    const float* Wl1 = (const float*)d_in[9];
    const float* bl1 = (const float*)d_in[10];
    const float* Wl2 = (const float*)d_in[11];
    const float* bl2 = (const float*)d_in[12];
    const float* Wd1 = (const float*)d_in[13];
    const float* bd1 = (const float*)d_in[14];
    const float* Wd2 = (const float*)d_in[15];
    const float* bd2 = (const float*)d_in[16];
    const float* Wd3 = (const float*)d_in[17];
    const float* bd3 = (const float*)d_in[18];
    float* out = (float*)d_out;

    static bool attr_set = false;
    if (!attr_set) {
        cudaFuncSetAttribute(gemm1_mma, cudaFuncAttributeMaxDynamicSharedMemorySize, SM_G1);
        attr_set = true;
    }

    setup_kernel<<<592, 256>>>(W1l, W1r, W2l, W2r);

    // GEMM1 (tensor pipe, fp16, fused convert, BK=64, B-fragment pipeline)
    gemm1_mma<<<(N_NODES + 127) / 128, 512, SM_G1>>>(x, N_NODES);

    edge_agg1<<<25000, 256>>>(ei);   // fp16 v4 reductions, 16 thr/edge

    // GEMM2 (tensor pipe, fused SAGE epilogue, 2-stage prefetch, 3 CTAs/SM)
    gemm2_mma<<<(N_NODES + 127) / 128, 256>>>(b1l, N_NODES);

    edge_agg2<<<6250, 256>>>(ei);    // fp16 v4 reductions, 4 thr/edge

    // pool + fused MLP (last-block ticket)
    {
        dim3 blk(32, 8);
        pool_kernel<<<(N_NODES + 127) / 128, blk>>>(bat, b2l,
            Wl1, bl1, Wl2, bl2, Wd1, bd1, Wd2, bd2, Wd3, bd3, out);
    }
}

// round 17
// speedup vs baseline: 1.2286x; 1.0208x over previous
#include <cuda_runtime.h>
#include <cuda_fp16.h>
#include <cstdint>

#define N_NODES  50000
#define N_EDGES  400000
#define N_HEDGES 200000
#define N_GRAPHS 64

// ============================ device scratch ===============================
__device__ __half g_w1[256 * 512];         // [W1l|W1r]^T fp16  [256 n][512 k]
__device__ __half g_w2[64 * 128];          // [W2l|W2r]^T fp16  [64 n][128 k]
__device__ __half g_y1l[N_NODES * 128];    // x@W1l (fp16, for edge gather)
__device__ __half g_y1r[N_NODES * 128];    // x@W1r (fp16)
__device__ __half g_agg1[N_NODES * 128];   // fp16 edge-sum accumulator
__device__ float  g_cnt[N_NODES];
__device__ __half g_y2l[N_NODES * 32];     // h1@W2l (fp16)
__device__ __half g_y2r[N_NODES * 32];     // h1@W2r (fp16)
__device__ __half g_agg2[N_NODES * 32];    // fp16 edge-sum accumulator
__device__ float  g_gsum[N_GRAPHS * 32];
__device__ float  g_gcnt[N_GRAPHS];
__device__ int    g_ticket;

// ============== setup: zero accumulators + weight conversion ===============
__global__ void setup_kernel(const float* __restrict__ W1l, const float* __restrict__ W1r,
                             const float* __restrict__ W2l, const float* __restrict__ W2r) {
    size_t i = (size_t)blockIdx.x * blockDim.x + threadIdx.x;
    size_t stride = (size_t)gridDim.x * blockDim.x;
    if (i == 0) g_ticket = 0;
    for (size_t k = i; k < (size_t)N_NODES * 64; k += stride) ((uint32_t*)g_agg1)[k] = 0u;
    for (size_t k = i; k < (size_t)N_NODES * 16; k += stride) ((uint32_t*)g_agg2)[k] = 0u;
    for (size_t k = i; k < (size_t)N_NODES;      k += stride) g_cnt[k]  = 0.f;
    for (size_t k = i; k < (size_t)N_GRAPHS * 32; k += stride) g_gsum[k] = 0.f;
    for (size_t k = i; k < (size_t)N_GRAPHS;      k += stride) g_gcnt[k] = 0.f;
    for (size_t idx = i; idx < 256 * 512; idx += stride) {
        int n = (int)(idx >> 9), k = (int)(idx & 511);
        float v = (n < 128) ? W1l[k * 128 + n] : W1r[k * 128 + (n - 128)];
        g_w1[idx] = __float2half_rn(v);
    }
    for (size_t idx = i; idx < 64 * 128; idx += stride) {
        int n = (int)(idx >> 7), k = (int)(idx & 127);
        float v = (n < 32) ? W2l[k * 32 + n] : W2r[k * 32 + (n - 32)];
        g_w2[idx] = __float2half_rn(v);
    }
}

// ============================ helpers ======================================
__device__ __forceinline__ uint32_t su32(const void* p) {
    return (uint32_t)__cvta_generic_to_shared(p);
}
__device__ __forceinline__ uint32_t pack_h2(__half a, __half b) {
    __half2 t = __halves2half2(a, b);
    return *(uint32_t*)&t;
}
__device__ __forceinline__ uint2 cvt4h(float4 v) {
    return make_uint2(pack_h2(__float2half_rn(v.x), __float2half_rn(v.y)),
                      pack_h2(__float2half_rn(v.z), __float2half_rn(v.w)));
}
__device__ __forceinline__ void mma16816h(float* c, const uint32_t* a, const uint32_t* b) {
    asm volatile(
        "mma.sync.aligned.m16n8k16.row.col.f32.f16.f16.f32 "
        "{%0,%1,%2,%3}, {%4,%5,%6,%7}, {%8,%9}, {%0,%1,%2,%3};"
        : "+f"(c[0]), "+f"(c[1]), "+f"(c[2]), "+f"(c[3])
        : "r"(a[0]), "r"(a[1]), "r"(a[2]), "r"(a[3]), "r"(b[0]), "r"(b[1]));
}
__device__ __forceinline__ void ldsm4(uint32_t* r, uint32_t addr) {
    asm volatile("ldmatrix.sync.aligned.m8n8.x4.shared.b16 {%0,%1,%2,%3}, [%4];"
                 : "=r"(r[0]), "=r"(r[1]), "=r"(r[2]), "=r"(r[3]) : "r"(addr));
}
__device__ __forceinline__ void red_h8(__half* p, uint4 v) {
    asm volatile("red.global.add.noftz.v4.f16x2 [%0], {%1,%2,%3,%4};"
                 :: "l"(p), "r"(v.x), "r"(v.y), "r"(v.z), "r"(v.w) : "memory");
}

// ===== GEMM1: [y1l|y1r] = x[M,512] @ W1^T  (fp16, fused convert, BK=64) ====
// 512 threads, CTA tile 128(M) x 256(N), BK=64, 2-stage, mid-loop store,
// B-fragment software pipeline in the inner loop.
#define G1_ROW 144
#define G1_STAGE 55296
#define SM_G1 (2 * G1_STAGE)

__global__ __launch_bounds__(512) void gemm1_mma(const float* __restrict__ x, int M) {
    extern __shared__ char smem[];
    const uint32_t sb = su32(smem);
    const int tid  = threadIdx.x;
    const int lane = tid & 31, wid = tid >> 5;
    const int wm = (wid & 3) * 32;
    const int wn = (wid >> 2) * 64;
    const int rowBase = blockIdx.x * 128;

    float acc[2][8][4];
#pragma unroll
    for (int i = 0; i < 2; i++)
#pragma unroll
        for (int j = 0; j < 8; j++)
#pragma unroll
            for (int q = 0; q < 4; q++) acc[i][j][q] = 0.f;

    const int g4 = lane & 3, gID = lane >> 2;
    const int sel = lane >> 3;
    const uint32_t rowInSel = (uint32_t)((sel & 1) * 8 + (lane & 7));
    const uint32_t colSel = (uint32_t)((sel >> 1) * 16);
    const uint32_t aOff = (wm + rowInSel) * G1_ROW + colSel;
    const uint32_t bOff = 18432 + (wn + rowInSel) * G1_ROW + colSel;

    const int arow = tid >> 2, aq = tid & 3;
    const int gra = rowBase + arow;
    const bool av = (gra < M);
    const size_t agi = (size_t)(av ? gra : 0) * 512 + aq * 16;
    const uint32_t sAo = arow * G1_ROW + aq * 32;
    const uint32_t bRow0 = tid >> 3, bQ = (uint32_t)(tid & 7);
    const size_t bgiBase = (size_t)bRow0 * 512 + bQ * 8;
    const uint32_t sBoBase = 18432 + bRow0 * G1_ROW + bQ * 16;

    float4 ra[4];
    uint4 rb[4];
    const float4 zf4 = make_float4(0.f, 0.f, 0.f, 0.f);

    auto loadRegs = [&](int kt) {
#pragma unroll
        for (int p = 0; p < 4; p++)
            ra[p] = av ? *(const float4*)(x + agi + kt + p * 4) : zf4;
#pragma unroll
        for (int p = 0; p < 4; p++)
            rb[p] = *(const uint4*)(g_w1 + bgiBase + (size_t)p * 64 * 512 + kt);
    };
    auto storeStage = [&](int s) {
        char* st = smem + s * G1_STAGE;
        uint2 h0 = cvt4h(ra[0]), h1 = cvt4h(ra[1]);
        *(uint4*)(st + sAo)      = make_uint4(h0.x, h0.y, h1.x, h1.y);
        h0 = cvt4h(ra[2]); h1 = cvt4h(ra[3]);
        *(uint4*)(st + sAo + 16) = make_uint4(h0.x, h0.y, h1.x, h1.y);
#pragma unroll
        for (int p = 0; p < 4; p++)
            *(uint4*)(st + sBoBase + p * (64 * G1_ROW)) = rb[p];
    };

    auto mmaStep = [&](uint32_t Ab, int kk2) {
        uint32_t a[2][4];
        ldsm4(a[0], Ab + aOff + kk2 * 32);
        ldsm4(a[1], Ab + aOff + 2304 + kk2 * 32);
        uint32_t bc[4];
        ldsm4(bc, Ab + bOff + kk2 * 32);
#pragma unroll
        for (int ntp = 0; ntp < 4; ntp++) {
            uint32_t bn[4];
            if (ntp < 3) ldsm4(bn, Ab + bOff + (ntp + 1) * 2304 + kk2 * 32);
            uint32_t b0[2] = {bc[0], bc[2]};
            uint32_t b1[2] = {bc[1], bc[3]};
            mma16816h(acc[0][2 * ntp],     a[0], b0);
            mma16816h(acc[1][2 * ntp],     a[1], b0);
            mma16816h(acc[0][2 * ntp + 1], a[0], b1);
            mma16816h(acc[1][2 * ntp + 1], a[1], b1);
            if (ntp < 3) { bc[0] = bn[0]; bc[1] = bn[1]; bc[2] = bn[2]; bc[3] = bn[3]; }
        }
    };

    loadRegs(0);
    storeStage(0);
    __syncthreads();

    for (int it = 0; it < 8; it++) {
        const int s = it & 1;
        if (it < 7) loadRegs((it + 1) * 64);

        const uint32_t Ab = sb + s * G1_STAGE;
        mmaStep(Ab, 0);
        mmaStep(Ab, 1);
        if (it < 7) storeStage(s ^ 1);
        mmaStep(Ab, 2);
        mmaStep(Ab, 3);
        __syncthreads();
    }

    // epilogue: cols < 128 -> y1l fp16 ; cols >= 128 -> y1r fp16
#pragma unroll
    for (int mt = 0; mt < 2; mt++) {
        int r0 = rowBase + wm + mt * 16 + gID;
#pragma unroll
        for (int nt = 0; nt < 8; nt++) {
            int cc = wn + nt * 8 + g4 * 2;
            uint32_t p0 = pack_h2(__float2half_rn(acc[mt][nt][0]),
                                  __float2half_rn(acc[mt][nt][1]));
            uint32_t p1 = pack_h2(__float2half_rn(acc[mt][nt][2]),
                                  __float2half_rn(acc[mt][nt][3]));
            if (wn < 128) {
                if (r0 < M)     *(uint32_t*)(g_y1l + (size_t)r0 * 128 + cc) = p0;
                if (r0 + 8 < M) *(uint32_t*)(g_y1l + (size_t)(r0 + 8) * 128 + cc) = p1;
            } else {
                int cr = cc - 128;
                if (r0 < M)     *(uint32_t*)(g_y1r + (size_t)r0 * 128 + cr) = p0;
                if (r0 + 8 < M) *(uint32_t*)(g_y1r + (size_t)(r0 + 8) * 128 + cr) = p1;
            }
        }
    }
}

// ===== GEMM2 (fused SAGE epilogue, 2-stage register-prefetch pipeline) =====
__global__ __launch_bounds__(256, 3) void gemm2_mma(const float* __restrict__ b1l, int M) {
    __shared__ __half sA[2][128][40], sB[2][64][40];

    const int tid  = threadIdx.x;
    const int lane = tid & 31, wid = tid >> 5;
    const int wm = (wid & 3) * 32;
    const int wn = (wid >> 2) * 32;
    const int rowBase = blockIdx.x * 128;

    float acc[2][4][4];
#pragma unroll
    for (int i = 0; i < 2; i++)
#pragma unroll
        for (int j = 0; j < 4; j++)
#pragma unroll
            for (int q = 0; q < 4; q++) acc[i][j][q] = 0.f;

    const int g4 = lane & 3, gID = lane >> 2;
    const int sel = lane >> 3;
    const uint32_t rowInSel = (uint32_t)((sel & 1) * 8 + (lane & 7));
    const uint32_t colSel = (uint32_t)((sel >> 1) * 16);
    const uint32_t aOff = (wm + rowInSel) * 80 + colSel;
    const uint32_t bOff = (wn + rowInSel) * 80 + colSel;
    const uint32_t aB0 = su32(sA), bB0 = su32(sB);

    const int arow0 = tid >> 2, aq = tid & 3;
    const int gr0 = rowBase + arow0, gr1 = gr0 + 64;
    const bool av0 = (gr0 < M), av1 = (gr1 < M);
    const float inv0 = av0 ? 1.0f / fmaxf(g_cnt[gr0], 1.0f) : 0.f;
    const float inv1 = av1 ? 1.0f / fmaxf(g_cnt[gr1], 1.0f) : 0.f;

    uint4  pagg[2];
    uint4  pr[2];
    float4 pbb[2];
    uint4  pwb;
    const int brow = tid >> 2, bq = tid & 3;

    auto loadRegs = [&](int kt) {
        const int kc = kt + aq * 8;
        pbb[0] = *(const float4*)(b1l + kc);
        pbb[1] = *(const float4*)(b1l + kc + 4);
#pragma unroll
        for (int p = 0; p < 2; p++) {
            const int gr = p ? gr1 : gr0;
            const bool av = p ? av1 : av0;
            if (av) {
                pagg[p] = *(const uint4*)(g_agg1 + (size_t)gr * 128 + kc);
                pr[p]   = *(const uint4*)(g_y1r + (size_t)gr * 128 + kc);
            } else {
                pagg[p] = make_uint4(0, 0, 0, 0);
                pr[p]   = make_uint4(0, 0, 0, 0);
            }
        }
        pwb = *(const uint4*)(g_w2 + (size_t)brow * 128 + kt + bq * 8);
    };
    auto storeStage = [&](int s) {
#pragma unroll
        for (int p = 0; p < 2; p++) {
            const bool av = p ? av1 : av0;
            const float inv = p ? inv1 : inv0;
            uint4 packed = make_uint4(0, 0, 0, 0);
            if (av) {
                const __half2* ah = (const __half2*)&pagg[p];
                const __half2* rh = (const __half2*)&pr[p];
                float2 a0 = __half22float2(ah[0]), a1 = __half22float2(ah[1]);
                float2 a2 = __half22float2(ah[2]), a3 = __half22float2(ah[3]);
                float2 r0 = __half22float2(rh[0]), r1 = __half22float2(rh[1]);
                float2 r2 = __half22float2(rh[2]), r3 = __half22float2(rh[3]);
                float4 o0, o1;
                o0.x = fmaxf(a0.x * inv + pbb[0].x + r0.x, 0.f);
                o0.y = fmaxf(a0.y * inv + pbb[0].y + r0.y, 0.f);
                o0.z = fmaxf(a1.x * inv + pbb[0].z + r1.x, 0.f);
                o0.w = fmaxf(a1.y * inv + pbb[0].w + r1.y, 0.f);
                o1.x = fmaxf(a2.x * inv + pbb[1].x + r2.x, 0.f);
                o1.y = fmaxf(a2.y * inv + pbb[1].y + r2.y, 0.f);
                o1.z = fmaxf(a3.x * inv + pbb[1].z + r3.x, 0.f);
                o1.w = fmaxf(a3.y * inv + pbb[1].w + r3.y, 0.f);
                uint2 h0 = cvt4h(o0), h1 = cvt4h(o1);
                packed = make_uint4(h0.x, h0.y, h1.x, h1.y);
            }
            *(uint4*)&sA[s][arow0 + p * 64][aq * 8] = packed;
        }
        *(uint4*)&sB[s][brow][bq * 8] = pwb;
    };

    loadRegs(0);
    storeStage(0);
    __syncthreads();

    for (int it = 0; it < 4; it++) {
        const int s = it & 1;
        if (it < 3) loadRegs((it + 1) * 32);

        const uint32_t aB = aB0 + (uint32_t)s * 10240;
        const uint32_t bB = bB0 + (uint32_t)s * 5120;
#pragma unroll
        for (int kk2 = 0; kk2 < 2; kk2++) {
            uint32_t a[2][4];
            ldsm4(a[0], aB + aOff + kk2 * 32);
            ldsm4(a[1], aB + aOff + 1280 + kk2 * 32);
#pragma unroll
            for (int ntp = 0; ntp < 2; ntp++) {
                uint32_t b[4];
                ldsm4(b, bB + bOff + ntp * 1280 + kk2 * 32);
                uint32_t b0[2] = {b[0], b[2]};
                uint32_t b1[2] = {b[1], b[3]};
                mma16816h(acc[0][2 * ntp],     a[0], b0);
                mma16816h(acc[1][2 * ntp],     a[1], b0);
                mma16816h(acc[0][2 * ntp + 1], a[0], b1);
                mma16816h(acc[1][2 * ntp + 1], a[1], b1);
            }
        }
        if (it < 3) storeStage(s ^ 1);
        __syncthreads();
    }

    // epilogue: cols < 32 -> y2l fp16 ; cols >= 32 -> y2r fp16
#pragma unroll
    for (int mt = 0; mt < 2; mt++) {
        int r0 = rowBase + wm + mt * 16 + gID;
#pragma unroll
        for (int nt = 0; nt < 4; nt++) {
            int cc = wn + nt * 8 + g4 * 2;
            uint32_t p0 = pack_h2(__float2half_rn(acc[mt][nt][0]),
                                  __float2half_rn(acc[mt][nt][1]));
            uint32_t p1 = pack_h2(__float2half_rn(acc[mt][nt][2]),
                                  __float2half_rn(acc[mt][nt][3]));
            if (cc < 32) {
                if (r0 < M)     *(uint32_t*)(g_y2l + (size_t)r0 * 32 + cc) = p0;
                if (r0 + 8 < M) *(uint32_t*)(g_y2l + (size_t)(r0 + 8) * 32 + cc) = p1;
            } else {
                int cr = cc - 32;
                if (r0 < M)     *(uint32_t*)(g_y2r + (size_t)r0 * 32 + cr) = p0;
                if (r0 + 8 < M) *(uint32_t*)(g_y2r + (size_t)(r0 + 8) * 32 + cr) = p1;
            }
        }
    }
}

// -------- edge aggregation, layer 1: 2 edges/thread, 16 threads/edge -------
__global__ void edge_agg1(const int* __restrict__ ei) {
    int gtid = blockIdx.x * blockDim.x + threadIdx.x;
    int e0 = gtid >> 4;
    int lane = gtid & 15;
    if (e0 >= N_HEDGES) return;
    int e1 = e0 + N_HEDGES;
    int s0 = ei[e0],            d0 = ei[N_EDGES + e0];
    int s1 = ei[e1],            d1 = ei[N_EDGES + e1];
    uint4 v0 = *(const uint4*)(g_y1l + (size_t)s0 * 128 + lane * 8);
    uint4 v1 = *(const uint4*)(g_y1l + (size_t)s1 * 128 + lane * 8);
    red_h8(g_agg1 + (size_t)d0 * 128 + lane * 8, v0);
    red_h8(g_agg1 + (size_t)d1 * 128 + lane * 8, v1);
    if (lane == 0) {
        atomicAdd(&g_cnt[d0], 1.0f);
        atomicAdd(&g_cnt[d1], 1.0f);
    }
}

// -------- edge aggregation, layer 2: 2 edges/thread, 4 threads/edge --------
__global__ void edge_agg2(const int* __restrict__ ei) {
    int gtid = blockIdx.x * blockDim.x + threadIdx.x;
    int e0 = gtid >> 2;
    int lane = gtid & 3;
    if (e0 >= N_HEDGES) return;
    int e1 = e0 + N_HEDGES;
    int s0 = ei[e0],            d0 = ei[N_EDGES + e0];
    int s1 = ei[e1],            d1 = ei[N_EDGES + e1];
    uint4 v0 = *(const uint4*)(g_y2l + (size_t)s0 * 32 + lane * 8);
    uint4 v1 = *(const uint4*)(g_y2l + (size_t)s1 * 32 + lane * 8);
    red_h8(g_agg2 + (size_t)d0 * 32 + lane * 8, v0);
    red_h8(g_agg2 + (size_t)d1 * 32 + lane * 8, v1);
}

// ====== fused layer-2 epilogue + per-graph mean pool + final MLP ===========
__global__ void pool_kernel(const int* __restrict__ batch, const float* __restrict__ b2l,
                            const float* __restrict__ Wl1, const float* __restrict__ bl1,
                            const float* __restrict__ Wl2, const float* __restrict__ bl2,
                            const float* __restrict__ Wd1, const float* __restrict__ bd1,
                            const float* __restrict__ Wd2, const float* __restrict__ bd2,
                            const float* __restrict__ Wd3, const float* __restrict__ bd3,
                            float* __restrict__ out) {
    __shared__ bool sLast;
    __shared__ float sWl1[1024], sWl2[512], sWd1[512], sWd2[1024], sWd3[1600];
    __shared__ float sbl1[32], sbl2[16], sbd1[32], sbd2[32], sbd3[50];

    int f = threadIdx.x;           // 32
    int yid = threadIdx.y;         // 8
    int tid = yid * 32 + f;        // 0..255
    int n0 = blockIdx.x * 128 + yid;
    float b = b2l[f];
    float acc = 0.f, cacc = 0.f;
    int cur = -1;
    for (int it = 0; it < 16; it++) {
        int n = n0 + it * 8;
        if (n < N_NODES) {
            int g = batch[n];
            if (g != cur) {
                if (cur >= 0) {
                    atomicAdd(&g_gsum[cur * 32 + f], acc);
                    if (f == 0) atomicAdd(&g_gcnt[cur], cacc);
                }
                cur = g; acc = 0.f; cacc = 0.f;
            }
            float inv = 1.0f / fmaxf(g_cnt[n], 1.0f);
            float v = __half2float(g_agg2[(size_t)n * 32 + f]) * inv + b +
                      __half2float(g_y2r[(size_t)n * 32 + f]);
            acc += fmaxf(v, 0.f);
            cacc += 1.f;
        }
    }
    if (cur >= 0) {
        atomicAdd(&g_gsum[cur * 32 + f], acc);
        if (f == 0) atomicAdd(&g_gcnt[cur], cacc);
    }

    __threadfence();
    __syncthreads();
    if (tid == 0) {
        int v = atomicAdd(&g_ticket, 1);
        sLast = (v == (int)gridDim.x - 1);
    }
    __syncthreads();
    if (!sLast) return;

    for (int i = tid; i < 1024; i += 256) sWl1[i] = Wl1[i];
    for (int i = tid; i < 512;  i += 256) sWl2[i] = Wl2[i];
    for (int i = tid; i < 512;  i += 256) sWd1[i] = Wd1[i];
    for (int i = tid; i < 1024; i += 256) sWd2[i] = Wd2[i];
    for (int i = tid; i < 1600; i += 256) sWd3[i] = Wd3[i];
    if (tid < 32) sbl1[tid] = bl1[tid];
    if (tid < 16) sbl2[tid] = bl2[tid];
    if (tid < 32) sbd1[tid] = bd1[tid];
    if (tid < 32) sbd2[tid] = bd2[tid];
    if (tid < 50) sbd3[tid] = bd3[tid];
    __syncthreads();
    if (tid >= N_GRAPHS) return;
    int t = tid;

    float gv[32];
    float inv = 1.0f / fmaxf(g_gcnt[t], 1.0f);
#pragma unroll
    for (int i = 0; i < 32; i++) gv[i] = g_gsum[t * 32 + i] * inv;

    float a[32];
#pragma unroll
    for (int j = 0; j < 32; j++) {
        float s = sbl1[j];
#pragma unroll
        for (int i = 0; i < 32; i++) s = fmaf(gv[i], sWl1[i * 32 + j], s);
        a[j] = fmaxf(s, 0.f);
    }
    float enc[16];
#pragma unroll
    for (int j = 0; j < 16; j++) {
        float s = sbl2[j];
#pragma unroll
        for (int i = 0; i < 32; i++) s = fmaf(a[i], sWl2[i * 16 + j], s);
        enc[j] = s > 0.f ? s : 0.1f * s;
    }
#pragma unroll
    for (int j = 0; j < 16; j++) out[t * 16 + j] = enc[j];

    float z1[32];
#pragma unroll
    for (int j = 0; j < 32; j++) {
        float s = sbd1[j];
#pragma unroll
        for (int i = 0; i < 16; i++) s = fmaf(enc[i], sWd1[i * 32 + j], s);
        z1[j] = s > 0.f ? s : 0.1f * s;
    }
    float z2[32];
#pragma unroll
    for (int j = 0; j < 32; j++) {
        float s = sbd2[j];
#pragma unroll
        for (int i = 0; i < 32; i++) s = fmaf(z1[i], sWd2[i * 32 + j], s);
        z2[j] = s > 0.f ? s : 0.1f * s;
    }
#pragma unroll
    for (int j = 0; j < 50; j++) {
        float s = sbd3[j];
#pragma unroll
        for (int i = 0; i < 32; i++) s = fmaf(z2[i], sWd3[i * 50 + j], s);
        out[1024 + t * 50 + j] = s;
    }
}

// ---------------- launch ----------------------------------------------------
extern "C" void kernel_launch(void* const* d_in, const int* in_sizes, int n_in,
                              void* d_out, int out_size) {
    const float* x   = (const float*)d_in[0];
    const int*   ei  = (const int*)d_in[1];
    const int*   bat = (const int*)d_in[2];
    const float* W1l = (const float*)d_in[3];
    const float* b1l = (const float*)d_in[4];
    const float* W1r = (const float*)d_in[5];
    const float* W2l = (const float*)d_in[6];
    const float* b2l = (const float*)d_in[7];
    const float* W2r = (const float*)d_in[8];
    const float* Wl1 = (const float*)d_in[9];
    const float* bl1 = (const float*)d_in[10];
    const float* Wl2 = (const float*)d_in[11];
    const float* bl2 = (const float*)d_in[12];
    const float* Wd1 = (const float*)d_in[13];
    const float* bd1 = (const float*)d_in[14];
    const float* Wd2 = (const float*)d_in[15];
    const float* bd2 = (const float*)d_in[16];
    const float* Wd3 = (const float*)d_in[17];
    const float* bd3 = (const float*)d_in[18];
    float* out = (float*)d_out;

    static bool attr_set = false;
    if (!attr_set) {
        cudaFuncSetAttribute(gemm1_mma, cudaFuncAttributeMaxDynamicSharedMemorySize, SM_G1);
        attr_set = true;
    }

    setup_kernel<<<592, 256>>>(W1l, W1r, W2l, W2r);

    // GEMM1 (tensor pipe, fp16, fused convert, BK=64, B-fragment pipeline)
    gemm1_mma<<<(N_NODES + 127) / 128, 512, SM_G1>>>(x, N_NODES);

    edge_agg1<<<12500, 256>>>(ei);   // 2 edges/thread, 16 thr/edge

    // GEMM2 (tensor pipe, fused SAGE epilogue, 2-stage prefetch, 3 CTAs/SM)
    gemm2_mma<<<(N_NODES + 127) / 128, 256>>>(b1l, N_NODES);

    edge_agg2<<<3125, 256>>>(ei);    // 2 edges/thread, 4 thr/edge

    // pool + fused MLP (last-block ticket)
    {
        dim3 blk(32, 8);
        pool_kernel<<<(N_NODES + 127) / 128, blk>>>(bat, b2l,
            Wl1, bl1, Wl2, bl2, Wd1, bd1, Wd2, bd2, Wd3, bd3, out);
    }
}